// round 14
// baseline (speedup 1.0000x reference)
#include <cuda_runtime.h>
#include <mma.h>
#include <math.h>
#include <stdint.h>

using namespace nvcuda;

// tcgen05 is only legal in arch-accelerated ('a') compile passes.
#if defined(__CUDA_ARCH_FEAT_SM103_ALL) || defined(__CUDA_ARCH_FEAT_SM100_ALL) || defined(__CUDA_ARCH_FEAT_SM101_ALL)
#define TC_OK 1
#else
#define TC_OK 0
#endif

#define TOKENS 8192
#define NEXP   64
#define TOPK   8
#define HID    2048
#define INTER  768
#define BM     128
#define MP_MAX 12      // m-pairs per expert

#define NT1 6      // gemm1 n-tiles (INTER/128)
#define KT1 64     // gemm1 k-chunks (HID/32)
#define NT2 8      // gemm2 n-tiles (HID/256)
#define KT2 24     // gemm2 k-chunks (INTER/32)

#define MAXROWS (TOKENS * TOPK + NEXP * 256)   // pair-tail slack

// ---------------- scratch (static device memory) ----------------
__device__ float g_xr[(size_t)TOKENS * HID];       // tf32-rounded X
__device__ float g_h[(size_t)MAXROWS * INTER];     // silu(gate)*up
__device__ float g_down[(size_t)MAXROWS * HID];
// pre-rounded + pre-swizzled weight tile images (SW128 K-major)
// gemm1: merged [gate(128 rows) | up(128 rows)] x 32k = 8192 floats per (e,nt,kc)
__device__ float g_wgu[(size_t)NEXP * NT1 * KT1 * 8192];
__device__ float g_wd [(size_t)NEXP * NT2 * KT2 * 8192];
__device__ int   g_row_src[MAXROWS];
__device__ int   g_slot_of[TOKENS * TOPK];
__device__ float g_wt[TOKENS * TOPK];
__device__ int   g_expert[TOKENS * TOPK];
__device__ int   g_cnt[NEXP];
__device__ int   g_cursor[NEXP];
__device__ int   g_off[NEXP + 1];

// ---------------- common PTX helpers ----------------
__device__ __forceinline__ uint32_t smem_u32(const void* p) {
    return (uint32_t)__cvta_generic_to_shared(p);
}
__device__ __forceinline__ void cp16(uint32_t dst, const void* src) {
    asm volatile("cp.async.cg.shared.global [%0], [%1], 16;" :: "r"(dst), "l"(src));
}
__device__ __forceinline__ void cp16z(uint32_t dst, const void* src) {
    asm volatile("cp.async.cg.shared.global [%0], [%1], 16, 0;" :: "r"(dst), "l"(src));
}
__device__ __forceinline__ void cp_commit() { asm volatile("cp.async.commit_group;"); }
__device__ __forceinline__ void cp_wait0()  { asm volatile("cp.async.wait_group 0;"); }
__device__ __forceinline__ void cp_wait1()  { asm volatile("cp.async.wait_group 1;"); }

__device__ __forceinline__ float tf32r(float x) {
    float r; asm("cvt.rna.tf32.f32 %0, %1;" : "=f"(r) : "f"(x)); return r;
}

// ---------------- small kernels ----------------
__global__ void k_zero() {
    int i = threadIdx.x;
    if (i < NEXP) { g_cnt[i] = 0; g_cursor[i] = 0; }
}

__global__ void k_route(const float* __restrict__ logits) {
    __shared__ int hist[NEXP];
    if (threadIdx.x < NEXP) hist[threadIdx.x] = 0;
    __syncthreads();

    int t = blockIdx.x * blockDim.x + threadIdx.x;
    if (t < TOKENS) {
        float l[NEXP];
#pragma unroll
        for (int i = 0; i < NEXP; i++) l[i] = logits[t * NEXP + i];
        float vals[TOPK]; int ids[TOPK];
#pragma unroll
        for (int k = 0; k < TOPK; k++) {
            float best = -INFINITY; int bi = 0;
#pragma unroll
            for (int i = 0; i < NEXP; i++)
                if (l[i] > best) { best = l[i]; bi = i; }
            vals[k] = best; ids[k] = bi; l[bi] = -INFINITY;
        }
        float m = vals[0], s = 0.f, ex[TOPK];
#pragma unroll
        for (int k = 0; k < TOPK; k++) { ex[k] = expf(vals[k] - m); s += ex[k]; }
        float inv = 1.f / s;
#pragma unroll
        for (int k = 0; k < TOPK; k++) {
            g_wt[t * TOPK + k] = ex[k] * inv;
            g_expert[t * TOPK + k] = ids[k];
            atomicAdd(&hist[ids[k]], 1);
        }
    }
    __syncthreads();
    if (threadIdx.x < NEXP && hist[threadIdx.x] > 0)
        atomicAdd(&g_cnt[threadIdx.x], hist[threadIdx.x]);
}

__global__ void k_scan() {
    if (threadIdx.x == 0) {
        int off = 0;
        for (int e = 0; e < NEXP; e++) {
            g_off[e] = off;
            off += ((g_cnt[e] + BM - 1) / BM) * BM;
        }
        g_off[NEXP] = off;
    }
}

__global__ void k_scatter() {
    int i = blockIdx.x * blockDim.x + threadIdx.x;
    if (i >= TOKENS * TOPK) return;
    int e = g_expert[i];
    int idx = atomicAdd(&g_cursor[e], 1);
    int slot = g_off[e] + idx;
    g_row_src[slot] = i / TOPK;
    g_slot_of[i] = slot;
}

__global__ void k_xround(const float* __restrict__ x) {
    size_t i = (size_t)blockIdx.x * blockDim.x + threadIdx.x;
    if (i >= (size_t)TOKENS * HID / 4) return;
    float4 v = ((const float4*)x)[i];
    v.x = tf32r(v.x); v.y = tf32r(v.y); v.z = tf32r(v.z); v.w = tf32r(v.w);
    ((float4*)g_xr)[i] = v;
}

// ---------------- weight prep: tf32-RN round + K-major SW128 tile bake ----------------
// gemm1 merged tile: rows 0..127 = gate n0..n0+127, rows 128..255 = up n0..n0+127,
// each row 32 k floats (128B), addr = n*128 + ((k*4)^((n&7)*16))
__global__ void __launch_bounds__(256) k_wprep1(const float* __restrict__ Wg,
                                                const float* __restrict__ Wu)
{
    int kc = blockIdx.x, nt = blockIdx.y, e = blockIdx.z;
    __shared__ float s[32][129];
    const float* srcs[2] = {
        Wg + (size_t)e * HID * INTER + (size_t)kc * 32 * INTER + nt * 128,
        Wu + (size_t)e * HID * INTER + (size_t)kc * 32 * INTER + nt * 128 };
    float* tile = g_wgu + (((size_t)e * NT1 + nt) * KT1 + kc) * 8192;

    for (int m = 0; m < 2; m++) {
        const float* src = srcs[m];
        float* dst = tile + m * 4096;   // gate at rows 0-127, up at rows 128-255
#pragma unroll
        for (int j = 0; j < 4; j++) {
            int idx = threadIdx.x + j * 256;
            int k = idx >> 5, c4 = idx & 31;
            float4 v = *(const float4*)(src + (size_t)k * INTER + c4 * 4);
            s[k][c4 * 4 + 0] = tf32r(v.x); s[k][c4 * 4 + 1] = tf32r(v.y);
            s[k][c4 * 4 + 2] = tf32r(v.z); s[k][c4 * 4 + 3] = tf32r(v.w);
        }
        __syncthreads();
#pragma unroll
        for (int j = 0; j < 4; j++) {
            int i = threadIdx.x + j * 256;
            int n = i >> 3, c = i & 7;
            float4 v = make_float4(s[c * 4 + 0][n], s[c * 4 + 1][n],
                                   s[c * 4 + 2][n], s[c * 4 + 3][n]);
            *(float4*)(dst + n * 32 + (((c * 16) ^ ((n & 7) * 16)) >> 2)) = v;
        }
        __syncthreads();
    }
}

__global__ void __launch_bounds__(256) k_wprep2(const float* __restrict__ Wd)
{
    int kc = blockIdx.x, nt = blockIdx.y, e = blockIdx.z;
    __shared__ float s[32][257];
    const float* src = Wd + (size_t)e * INTER * HID + (size_t)kc * 32 * HID + nt * 256;
    float* dst = g_wd + (((size_t)e * NT2 + nt) * KT2 + kc) * 8192;
#pragma unroll
    for (int j = 0; j < 8; j++) {
        int idx = threadIdx.x + j * 256;
        int k = idx >> 6, c4 = idx & 63;
        float4 v = *(const float4*)(src + (size_t)k * HID + c4 * 4);
        s[k][c4 * 4 + 0] = tf32r(v.x); s[k][c4 * 4 + 1] = tf32r(v.y);
        s[k][c4 * 4 + 2] = tf32r(v.z); s[k][c4 * 4 + 3] = tf32r(v.w);
    }
    __syncthreads();
#pragma unroll
    for (int j = 0; j < 8; j++) {
        int i = threadIdx.x + j * 256;
        int n = i >> 3, c = i & 7;
        float4 v = make_float4(s[c * 4 + 0][n], s[c * 4 + 1][n],
                               s[c * 4 + 2][n], s[c * 4 + 3][n]);
        *(float4*)(dst + n * 32 + (((c * 16) ^ ((n & 7) * 16)) >> 2)) = v;
    }
}

__global__ void k_combine(float* __restrict__ out) {
    int idx = blockIdx.x * blockDim.x + threadIdx.x;
    const int VPT = HID / 4;
    if (idx >= TOKENS * VPT) return;
    int t = idx / VPT;
    int c = (idx % VPT) * 4;
    float4 acc = make_float4(0.f, 0.f, 0.f, 0.f);
#pragma unroll
    for (int k = 0; k < TOPK; k++) {
        int slot = g_slot_of[t * TOPK + k];
        float w = g_wt[t * TOPK + k];
        float4 v = *(const float4*)(g_down + (size_t)slot * HID + c);
        acc.x += w * v.x; acc.y += w * v.y; acc.z += w * v.z; acc.w += w * v.w;
    }
    *(float4*)(out + (size_t)t * HID + c) = acc;
}

// ============================================================================
// tcgen05 path (bodies only in 'a' passes)
// ============================================================================
#if TC_OK
__device__ __forceinline__ uint32_t elect_one() {
    uint32_t p;
    asm volatile("{\n\t.reg .pred p;\n\telect.sync _|p, 0xFFFFFFFF;\n\tselp.b32 %0, 1, 0, p;\n\t}" : "=r"(p));
    return p;
}

#define MBAR_INIT(addr, cnt) \
    asm volatile("mbarrier.init.shared.b64 [%0], %1;" :: "r"(addr), "r"(cnt) : "memory")
#define MBAR_WAIT(addr, parity) do { \
    uint32_t _m = (addr), _p = (parity); \
    asm volatile("{\n\t.reg .pred P;\n\tWL_%=:\n\t" \
        "mbarrier.try_wait.parity.acquire.cta.shared::cta.b64 P, [%0], %1, 0x989680;\n\t" \
        "@P bra.uni WD_%=;\n\tbra.uni WL_%=;\n\tWD_%=:\n\t}" \
        :: "r"(_m), "r"(_p) : "memory"); } while (0)

#define TC_ALLOC(dst, n)  asm volatile("tcgen05.alloc.cta_group::1.sync.aligned.shared::cta.b32 [%0], %1;" :: "r"(dst), "r"(n) : "memory")
#define TC_DEALLOC(t, n)  asm volatile("tcgen05.dealloc.cta_group::1.sync.aligned.b32 %0, %1;" :: "r"(t), "r"(n))
#define TC_RELINQ()       asm volatile("tcgen05.relinquish_alloc_permit.cta_group::1.sync.aligned;")
#define TC_COMMIT(mb)     asm volatile("tcgen05.commit.cta_group::1.mbarrier::arrive::one.shared::cluster.b64 [%0];" :: "r"(mb) : "memory")
#define TC_FENCE_AFTER()  asm volatile("tcgen05.fence::after_thread_sync;" ::: "memory")
#define TC_FENCE_BEFORE() asm volatile("tcgen05.fence::before_thread_sync;" ::: "memory")
#define TC_WAIT_LD()      asm volatile("tcgen05.wait::ld.sync.aligned;" ::: "memory")
#define FENCE_ASYNC()     asm volatile("fence.proxy.async.shared::cta;" ::: "memory")

#define TC_LD_X16(r, addr) \
    asm volatile("tcgen05.ld.sync.aligned.32x32b.x16.b32 " \
        "{%0,%1,%2,%3,%4,%5,%6,%7,%8,%9,%10,%11,%12,%13,%14,%15}, [%16];" \
        : "=r"((r)[0]), "=r"((r)[1]), "=r"((r)[2]), "=r"((r)[3]), \
          "=r"((r)[4]), "=r"((r)[5]), "=r"((r)[6]), "=r"((r)[7]), \
          "=r"((r)[8]), "=r"((r)[9]), "=r"((r)[10]), "=r"((r)[11]), \
          "=r"((r)[12]), "=r"((r)[13]), "=r"((r)[14]), "=r"((r)[15]) \
        : "r"(addr))

#define TC_LD_X32(r, addr) \
    asm volatile("tcgen05.ld.sync.aligned.32x32b.x32.b32 " \
        "{%0,%1,%2,%3,%4,%5,%6,%7,%8,%9,%10,%11,%12,%13,%14,%15," \
        "%16,%17,%18,%19,%20,%21,%22,%23,%24,%25,%26,%27,%28,%29,%30,%31}, [%32];" \
        : "=r"((r)[0]), "=r"((r)[1]), "=r"((r)[2]), "=r"((r)[3]), \
          "=r"((r)[4]), "=r"((r)[5]), "=r"((r)[6]), "=r"((r)[7]), \
          "=r"((r)[8]), "=r"((r)[9]), "=r"((r)[10]), "=r"((r)[11]), \
          "=r"((r)[12]), "=r"((r)[13]), "=r"((r)[14]), "=r"((r)[15]), \
          "=r"((r)[16]), "=r"((r)[17]), "=r"((r)[18]), "=r"((r)[19]), \
          "=r"((r)[20]), "=r"((r)[21]), "=r"((r)[22]), "=r"((r)[23]), \
          "=r"((r)[24]), "=r"((r)[25]), "=r"((r)[26]), "=r"((r)[27]), \
          "=r"((r)[28]), "=r"((r)[29]), "=r"((r)[30]), "=r"((r)[31]) \
        : "r"(addr))

__device__ __forceinline__ void mma_tf32(uint32_t d_tmem, uint64_t a_desc, uint64_t b_desc,
                                         uint32_t idesc, bool acc) {
    uint32_t en = acc ? 1u : 0u;
    asm volatile("{\n\t.reg .pred p;\n\tsetp.ne.u32 p, %5, 0;\n\t"
                 "tcgen05.mma.cta_group::1.kind::tf32 [%0], %1, %2, %3, {%4, %4, %4, %4}, p;\n\t}"
                 :: "r"(d_tmem), "l"(a_desc), "l"(b_desc), "r"(idesc), "r"(0u), "r"(en)
                 : "memory");
}

__device__ __forceinline__ uint64_t mkdesc(uint32_t addr) {
    const uint64_t base = (2ull << 61) | (1ull << 46) | (64ull << 32) | (1ull << 16);
    return base | ((uint64_t)(addr >> 4) & 0x3FFF);
}

#define IDESC_N256 ((1u << 4) | (2u << 7) | (2u << 10) | (32u << 17) | (8u << 24))
#endif  // TC_OK

// ---------------- GEMM1 tcgen05: gate+up merged N=256, M=256, BK=32, 3-stage ----------------
// TMEM: [0:256)=D0 [gate|up], [256:512)=D1 [gate|up]
__global__ void __launch_bounds__(256, 1) k_gemm1_tc(const float* __restrict__ WgU,
                                                     const float* __restrict__ WuU)
{
#if TC_OK
    int e = blockIdx.z;
    int cnt = g_cnt[e];
    int mpair = blockIdx.x;
    if (mpair * 256 >= cnt) return;
    int base = g_off[e];
    int ntiles = (cnt + 127) >> 7;
    int nt = blockIdx.y;
    int n0 = nt * 128;

    extern __shared__ char dsm[];
    __shared__ uint32_t s_tmem;
    __shared__ uint64_t s_mbar[3];
    uint32_t sbase = (smem_u32(dsm) + 1023) & ~1023u;
    // per stage (64KB): A0 @0, A1 @16K, B(merged 256 rows) @32K
    uint32_t stg[3] = { sbase, sbase + 65536, sbase + 131072 };

    int tid = threadIdx.x, wid = tid >> 5, lane = tid & 31;

    if (tid == 0) {
        MBAR_INIT(smem_u32(&s_mbar[0]), 1);
        MBAR_INIT(smem_u32(&s_mbar[1]), 1);
        MBAR_INIT(smem_u32(&s_mbar[2]), 1);
    }
    if (wid == 0) { TC_ALLOC(smem_u32(&s_tmem), 512); TC_RELINQ(); }
    __syncthreads();
    uint32_t tmem = s_tmem;

    // A gather map: 8 rows per thread across 256 rows
    int c8 = tid & 7;
    const float* asrc[8];
    uint32_t adst[8];
#pragma unroll
    for (int p = 0; p < 8; p++) {
        int r = (tid >> 3) + p * 32;            // 0..255
        int gr = mpair * 256 + r;
        int s = (gr < cnt) ? g_row_src[base + gr] : -1;
        asrc[p] = (s >= 0) ? (g_xr + (size_t)s * HID + c8 * 4) : nullptr;
        int lr = r & 127;
        adst[p] = (uint32_t)((r >> 7) * 16384 + lr * 128 + ((c8 ^ (lr & 7)) * 16));
    }

    // merged B tile stream: 8192 floats (32KB) per k-chunk, 8 float4 per thread
    const float* tb = g_wgu + (((size_t)e * NT1 + nt) * KT1) * 8192 + tid * 32;
    uint32_t bdst = (uint32_t)(tid * 128);

    auto load_stage = [&](uint32_t bb, int it) {
        int k0 = it * 32;
#pragma unroll
        for (int p = 0; p < 8; p++) {
            if (asrc[p]) cp16(bb + adst[p], asrc[p] + k0);
            else         cp16z(bb + adst[p], g_xr);
        }
        const float* pb = tb + (size_t)it * 8192;
#pragma unroll
        for (int j = 0; j < 8; j++)
            cp16(bb + 32768 + bdst + j * 16, pb + j * 4);
        cp_commit();
    };

    const int KT = KT1;   // 64
    int ph[3] = { 0, 0, 0 };

    load_stage(stg[0], 0);
    load_stage(stg[1], 1);

    for (int it = 0; it < KT; it++) {
        int s = it % 3;
        uint32_t bb = stg[s];
        // Last iteration has only ONE group in flight — drain fully there.
        if (it == KT - 1) cp_wait0(); else cp_wait1();
        __syncthreads();

        if (wid == 0) {
            FENCE_ASYNC();
            if (elect_one()) {
                uint64_t da0 = mkdesc(bb);
                uint64_t da1 = mkdesc(bb + 16384);
                uint64_t db  = mkdesc(bb + 32768);
#pragma unroll
                for (int ks = 0; ks < 4; ks++) {
                    bool acc = !(it == 0 && ks == 0);
                    mma_tf32(tmem,       da0 + 2 * ks, db + 2 * ks, IDESC_N256, acc);
                    mma_tf32(tmem + 256, da1 + 2 * ks, db + 2 * ks, IDESC_N256, acc);
                }
                TC_COMMIT(smem_u32(&s_mbar[s]));
            }
        }

        int nx = it + 2;
        if (nx < KT) {
            int sn = nx % 3;     // == (it-1)%3 for it>=1
            if (it >= 1) { MBAR_WAIT(smem_u32(&s_mbar[sn]), ph[sn]); ph[sn] ^= 1; }
            load_stage(stg[sn], nx);
        }
    }

    int ls = (KT - 1) % 3;
    MBAR_WAIT(smem_u32(&s_mbar[ls]), ph[ls]);
    TC_FENCE_AFTER();

    if (wid < 4) {
        int m = wid * 32 + lane;
#pragma unroll
        for (int t = 0; t < 2; t++) {
            int mt = mpair * 2 + t;
            if (mt >= ntiles) break;
            float* dst = g_h + (size_t)(base + mt * 128 + m) * INTER + n0;
#pragma unroll
            for (int c0 = 0; c0 < 128; c0 += 16) {
                uint32_t rg[16], ru[16];
                TC_LD_X16(rg, tmem + t * 256 + c0);          // gate cols
                TC_LD_X16(ru, tmem + t * 256 + 128 + c0);    // up cols
                TC_WAIT_LD();
#pragma unroll
                for (int j = 0; j < 16; j++) {
                    float g = __uint_as_float(rg[j]);
                    float u = __uint_as_float(ru[j]);
                    float h = (g / (1.f + __expf(-g))) * u;
                    rg[j] = __float_as_uint(tf32r(h));
                }
#pragma unroll
                for (int j = 0; j < 16; j += 4)
                    *(uint4*)(dst + c0 + j) = make_uint4(rg[j], rg[j+1], rg[j+2], rg[j+3]);
            }
        }
        TC_FENCE_BEFORE();
    }
    __syncthreads();
    if (wid == 0) TC_DEALLOC(tmem, 512);
#endif
}

// ---------------- GEMM2 tcgen05: down, M=256, BN=256, BK=32, 3-stage ----------------
// TMEM: [0:256)=D0, [256:512)=D1
__global__ void __launch_bounds__(256, 1) k_gemm2_tc(const float* __restrict__ WdU)
{
#if TC_OK
    int e = blockIdx.z;
    int cnt = g_cnt[e];
    int mpair = blockIdx.x;
    if (mpair * 256 >= cnt) return;
    int base = g_off[e];
    int ntiles = (cnt + 127) >> 7;
    int nt = blockIdx.y;
    int n0 = nt * 256;

    extern __shared__ char dsm[];
    __shared__ uint32_t s_tmem;
    __shared__ uint64_t s_mbar[3];
    uint32_t sbase = (smem_u32(dsm) + 1023) & ~1023u;
    uint32_t stg[3] = { sbase, sbase + 65536, sbase + 131072 };

    int tid = threadIdx.x, wid = tid >> 5, lane = tid & 31;

    if (tid == 0) {
        MBAR_INIT(smem_u32(&s_mbar[0]), 1);
        MBAR_INIT(smem_u32(&s_mbar[1]), 1);
        MBAR_INIT(smem_u32(&s_mbar[2]), 1);
    }
    if (wid == 0) { TC_ALLOC(smem_u32(&s_tmem), 512); TC_RELINQ(); }
    __syncthreads();
    uint32_t tmem = s_tmem;

    int c8 = tid & 7;
    const float* asrc[8];
    uint32_t adst[8];
#pragma unroll
    for (int p = 0; p < 8; p++) {
        int r = (tid >> 3) + p * 32;
        asrc[p] = g_h + (size_t)(base + mpair * 256 + r) * INTER + c8 * 4;
        int lr = r & 127;
        adst[p] = (uint32_t)((r >> 7) * 16384 + lr * 128 + ((c8 ^ (lr & 7)) * 16));
    }

    const float* td = g_wd + (((size_t)e * NT2 + nt) * KT2) * 8192 + tid * 32;
    uint32_t bdst = (uint32_t)(tid * 128);

    auto load_stage = [&](uint32_t bb, int it) {
        int k0 = it * 32;
#pragma unroll
        for (int p = 0; p < 8; p++)
            cp16(bb + adst[p], asrc[p] + k0);
        const float* pw = td + (size_t)it * 8192;
#pragma unroll
        for (int j = 0; j < 8; j++)
            cp16(bb + 32768 + bdst + j * 16, pw + j * 4);
        cp_commit();
    };

    const int KT = KT2;   // 24
    int ph[3] = { 0, 0, 0 };

    load_stage(stg[0], 0);
    load_stage(stg[1], 1);

    for (int it = 0; it < KT; it++) {
        int s = it % 3;
        uint32_t bb = stg[s];
        if (it == KT - 1) cp_wait0(); else cp_wait1();
        __syncthreads();

        if (wid == 0) {
            FENCE_ASYNC();
            if (elect_one()) {
                uint64_t da0 = mkdesc(bb);
                uint64_t da1 = mkdesc(bb + 16384);
                uint64_t db  = mkdesc(bb + 32768);
#pragma unroll
                for (int ks = 0; ks < 4; ks++) {
                    bool acc = !(it == 0 && ks == 0);
                    mma_tf32(tmem,       da0 + 2 * ks, db + 2 * ks, IDESC_N256, acc);
                    mma_tf32(tmem + 256, da1 + 2 * ks, db + 2 * ks, IDESC_N256, acc);
                }
                TC_COMMIT(smem_u32(&s_mbar[s]));
            }
        }

        int nx = it + 2;
        if (nx < KT) {
            int sn = nx % 3;
            if (it >= 1) { MBAR_WAIT(smem_u32(&s_mbar[sn]), ph[sn]); ph[sn] ^= 1; }
            load_stage(stg[sn], nx);
        }
    }

    int ls = (KT - 1) % 3;
    MBAR_WAIT(smem_u32(&s_mbar[ls]), ph[ls]);
    TC_FENCE_AFTER();

    if (wid < 4) {
        int m = wid * 32 + lane;
#pragma unroll
        for (int t = 0; t < 2; t++) {
            int mt = mpair * 2 + t;
            if (mt >= ntiles) break;
            float* dst = g_down + (size_t)(base + mt * 128 + m) * HID + n0;
#pragma unroll
            for (int c0 = 0; c0 < 256; c0 += 32) {
                uint32_t r[32];
                TC_LD_X32(r, tmem + t * 256 + c0);
                TC_WAIT_LD();
#pragma unroll
                for (int j = 0; j < 32; j += 4)
                    *(uint4*)(dst + c0 + j) = make_uint4(r[j], r[j+1], r[j+2], r[j+3]);
            }
        }
        TC_FENCE_BEFORE();
    }
    __syncthreads();
    if (wid == 0) TC_DEALLOC(tmem, 512);
#endif
}

// ============================================================================
// wmma fallback path (bodies only in non-'a' device passes; reads raw weights)
// ============================================================================
#define FBK 16

__global__ void __launch_bounds__(256) k_gemm1_wm(
    const float* __restrict__ x,
    const float* __restrict__ Wg,
    const float* __restrict__ Wu)
{
#if !TC_OK
    int e = blockIdx.z;
    int cnt = g_cnt[e];
    if ((int)blockIdx.x * BM >= cnt) return;
    int base = g_off[e];
    int n0 = blockIdx.y * 64;

    __shared__ float sA [2][BM][FBK + 4];
    __shared__ float sBg[2][FBK][64 + 4];
    __shared__ float sBu[2][FBK][64 + 4];

    int tid = threadIdx.x;
    int wid = tid >> 5;
    int wm = wid >> 1;
    int wn = wid & 1;

    int arow = tid >> 2;
    int acol = (tid & 3) << 2;
    const float* aptr[2];
#pragma unroll
    for (int p = 0; p < 2; p++) {
        int r = blockIdx.x * BM + p * 64 + arow;
        int s = (r < cnt) ? g_row_src[base + r] : -1;
        aptr[p] = (s >= 0) ? (x + (size_t)s * HID + acol) : nullptr;
    }
    int brow = tid >> 4;
    int bcol = (tid & 15) << 2;
    const float* bg = Wg + (size_t)e * HID * INTER + (size_t)brow * INTER + n0 + bcol;
    const float* bu = Wu + (size_t)e * HID * INTER + (size_t)brow * INTER + n0 + bcol;

    wmma::fragment<wmma::accumulator, 16, 16, 8, float> accG[2][2], accU[2][2];
#pragma unroll
    for (int im = 0; im < 2; im++)
#pragma unroll
        for (int in = 0; in < 2; in++) {
            wmma::fill_fragment(accG[im][in], 0.f);
            wmma::fill_fragment(accU[im][in], 0.f);
        }

    auto load_tile = [&](int buf, int k0) {
#pragma unroll
        for (int p = 0; p < 2; p++) {
            uint32_t d = smem_u32(&sA[buf][p * 64 + arow][acol]);
            if (aptr[p]) cp16(d, aptr[p] + k0);
            else         cp16z(d, x);
        }
        cp16(smem_u32(&sBg[buf][brow][bcol]), bg + (size_t)k0 * INTER);
        cp16(smem_u32(&sBu[buf][brow][bcol]), bu + (size_t)k0 * INTER);
    };

    load_tile(0, 0);
    cp_commit();

    int buf = 0;
    for (int k0 = 0; k0 < HID; k0 += FBK) {
        cp_wait0();
        __syncthreads();
        if (k0 + FBK < HID) { load_tile(buf ^ 1, k0 + FBK); cp_commit(); }

#pragma unroll
        for (int kk = 0; kk < FBK; kk += 8) {
            wmma::fragment<wmma::matrix_a, 16, 16, 8, wmma::precision::tf32, wmma::row_major> a[2];
            wmma::fragment<wmma::matrix_b, 16, 16, 8, wmma::precision::tf32, wmma::row_major> fg[2], fu[2];
#pragma unroll
            for (int im = 0; im < 2; im++) {
                wmma::load_matrix_sync(a[im], &sA[buf][wm * 32 + im * 16][kk], FBK + 4);
#pragma unroll
                for (int i = 0; i < a[im].num_elements; i++)
                    a[im].x[i] = wmma::__float_to_tf32(a[im].x[i]);
            }
#pragma unroll
            for (int in = 0; in < 2; in++) {
                wmma::load_matrix_sync(fg[in], &sBg[buf][kk][wn * 32 + in * 16], 64 + 4);
                wmma::load_matrix_sync(fu[in], &sBu[buf][kk][wn * 32 + in * 16], 64 + 4);
#pragma unroll
                for (int i = 0; i < fg[in].num_elements; i++) {
                    fg[in].x[i] = wmma::__float_to_tf32(fg[in].x[i]);
                    fu[in].x[i] = wmma::__float_to_tf32(fu[in].x[i]);
                }
            }
#pragma unroll
            for (int im = 0; im < 2; im++)
#pragma unroll
                for (int in = 0; in < 2; in++) {
                    wmma::mma_sync(accG[im][in], a[im], fg[in], accG[im][in]);
                    wmma::mma_sync(accU[im][in], a[im], fu[in], accU[im][in]);
                }
        }
        buf ^= 1;
    }

#pragma unroll
    for (int im = 0; im < 2; im++)
#pragma unroll
        for (int in = 0; in < 2; in++) {
#pragma unroll
            for (int i = 0; i < accG[im][in].num_elements; i++) {
                float g = accG[im][in].x[i];
                float u = accU[im][in].x[i];
                accG[im][in].x[i] = (g / (1.f + expf(-g))) * u;
            }
            size_t row = (size_t)base + blockIdx.x * BM + wm * 32 + im * 16;
            wmma::store_matrix_sync(g_h + row * INTER + n0 + wn * 32 + in * 16,
                                    accG[im][in], INTER, wmma::mem_row_major);
        }
#endif
}

__global__ void __launch_bounds__(256) k_gemm2_wm(const float* __restrict__ Wd)
{
#if !TC_OK
    int e = blockIdx.z;
    int cnt = g_cnt[e];
    if ((int)blockIdx.x * BM >= cnt) return;
    int base = g_off[e];
    int n0 = blockIdx.y * 64;

    __shared__ float sA[2][BM][FBK + 4];
    __shared__ float sB[2][FBK][64 + 4];

    int tid = threadIdx.x;
    int wid = tid >> 5;
    int wm = wid >> 1;
    int wn = wid & 1;

    int arow = tid >> 2;
    int acol = (tid & 3) << 2;
    const float* A = g_h + (size_t)(base + blockIdx.x * BM) * INTER;

    int brow = tid >> 4;
    int bcol = (tid & 15) << 2;
    const float* B = Wd + (size_t)e * INTER * HID + (size_t)brow * HID + n0 + bcol;

    wmma::fragment<wmma::accumulator, 16, 16, 8, float> acc[2][2];
#pragma unroll
    for (int im = 0; im < 2; im++)
#pragma unroll
        for (int in = 0; in < 2; in++)
            wmma::fill_fragment(acc[im][in], 0.f);

    auto load_tile = [&](int buf, int k0) {
#pragma unroll
        for (int p = 0; p < 2; p++) {
            int r = p * 64 + arow;
            cp16(smem_u32(&sA[buf][r][acol]), A + (size_t)r * INTER + k0 + acol);
        }
        cp16(smem_u32(&sB[buf][brow][bcol]), B + (size_t)k0 * HID);
    };

    load_tile(0, 0);
    cp_commit();

    int buf = 0;
    for (int k0 = 0; k0 < INTER; k0 += FBK) {
        cp_wait0();
        __syncthreads();
        if (k0 + FBK < INTER) { load_tile(buf ^ 1, k0 + FBK); cp_commit(); }

#pragma unroll
        for (int kk = 0; kk < FBK; kk += 8) {
            wmma::fragment<wmma::matrix_a, 16, 16, 8, wmma::precision::tf32, wmma::row_major> a[2];
            wmma::fragment<wmma::matrix_b, 16, 16, 8, wmma::precision::tf32, wmma::row_major> b[2];
#pragma unroll
            for (int im = 0; im < 2; im++) {
                wmma::load_matrix_sync(a[im], &sA[buf][wm * 32 + im * 16][kk], FBK + 4);
#pragma unroll
                for (int i = 0; i < a[im].num_elements; i++)
                    a[im].x[i] = wmma::__float_to_tf32(a[im].x[i]);
            }
#pragma unroll
            for (int in = 0; in < 2; in++) {
                wmma::load_matrix_sync(b[in], &sB[buf][kk][wn * 32 + in * 16], 64 + 4);
#pragma unroll
                for (int i = 0; i < b[in].num_elements; i++)
                    b[in].x[i] = wmma::__float_to_tf32(b[in].x[i]);
            }
#pragma unroll
            for (int im = 0; im < 2; im++)
#pragma unroll
                for (int in = 0; in < 2; in++)
                    wmma::mma_sync(acc[im][in], a[im], b[in], acc[im][in]);
        }
        buf ^= 1;
    }

#pragma unroll
    for (int im = 0; im < 2; im++)
#pragma unroll
        for (int in = 0; in < 2; in++) {
            size_t row = (size_t)base + blockIdx.x * BM + wm * 32 + im * 16;
            wmma::store_matrix_sync(g_down + row * HID + n0 + wn * 32 + in * 16,
                                    acc[im][in], HID, wmma::mem_row_major);
        }
#endif
}

// ---------------- launch ----------------
extern "C" void kernel_launch(void* const* d_in, const int* in_sizes, int n_in,
                              void* d_out, int out_size)
{
    const float* x      = (const float*)d_in[0];
    const float* logits = (const float*)d_in[1];
    const float* Wg     = (const float*)d_in[2];
    const float* Wu     = (const float*)d_in[3];
    const float* Wd     = (const float*)d_in[4];
    float* out = (float*)d_out;

    cudaFuncSetAttribute(k_gemm1_tc, cudaFuncAttributeMaxDynamicSharedMemorySize, 197632);
    cudaFuncSetAttribute(k_gemm2_tc, cudaFuncAttributeMaxDynamicSharedMemorySize, 197632);

    k_zero<<<1, 64>>>();
    k_route<<<(TOKENS + 127) / 128, 128>>>(logits);
    k_scan<<<1, 32>>>();
    k_scatter<<<(TOKENS * TOPK + 255) / 256, 256>>>();
    k_xround<<<(TOKENS * HID / 4 + 255) / 256, 256>>>(x);

    // weight prep: tf32-RN round + K-major SW128 tile bake
    dim3 gp1(KT1, NT1, NEXP);
    k_wprep1<<<gp1, 256>>>(Wg, Wu);
    dim3 gp2(KT2, NT2, NEXP);
    k_wprep2<<<gp2, 256>>>(Wd);

    // tcgen05 path (no-op in non-'a' cubins)
    dim3 g1t(MP_MAX, NT1, NEXP);
    k_gemm1_tc<<<g1t, 256, 197632>>>(Wg, Wu);
    dim3 g2t(MP_MAX, NT2, NEXP);
    k_gemm2_tc<<<g2t, 256, 197632>>>(Wd);

    // wmma fallback path (no-op in 'a' cubins)
    dim3 g1w(TOKENS / BM, INTER / 64, NEXP);
    k_gemm1_wm<<<g1w, 256>>>(x, Wg, Wu);
    dim3 g2w(TOKENS / BM, HID / 64, NEXP);
    k_gemm2_wm<<<g2w, 256>>>(Wd);

    int tot = TOKENS * (HID / 4);
    k_combine<<<(tot + 255) / 256, 256>>>(out);
}

// round 16
// speedup vs baseline: 1.4049x; 1.4049x over previous
#include <cuda_runtime.h>
#include <mma.h>
#include <math.h>
#include <stdint.h>

using namespace nvcuda;

// tcgen05 is only legal in arch-accelerated ('a') compile passes.
#if defined(__CUDA_ARCH_FEAT_SM103_ALL) || defined(__CUDA_ARCH_FEAT_SM100_ALL) || defined(__CUDA_ARCH_FEAT_SM101_ALL)
#define TC_OK 1
#else
#define TC_OK 0
#endif

#define TOKENS 8192
#define NEXP   64
#define TOPK   8
#define HID    2048
#define INTER  768
#define BM     128
#define MP_MAX 12      // m-pairs per expert

#define NT1 6      // gemm1 n-tiles (INTER/128)
#define KT1 64     // gemm1 k-chunks (HID/32)
#define NT2 8      // gemm2 n-tiles (HID/256)
#define KT2 24     // gemm2 k-chunks (INTER/32)

#define MAXROWS (TOKENS * TOPK + NEXP * 256)   // pair-tail slack

// ---------------- scratch (static device memory) ----------------
__device__ float g_xr[(size_t)TOKENS * HID];       // tf32-rounded X
__device__ float g_h[(size_t)MAXROWS * INTER];     // silu(gate)*up
__device__ float g_down[(size_t)MAXROWS * HID];
// pre-rounded + pre-swizzled weight tile images (SW128 K-major)
// gemm1: merged [gate(128 rows) | up(128 rows)] x 32k = 8192 floats per (e,nt,kc)
__device__ float g_wgu[(size_t)NEXP * NT1 * KT1 * 8192];
__device__ float g_wd [(size_t)NEXP * NT2 * KT2 * 8192];
__device__ int   g_row_src[MAXROWS];
__device__ int   g_slot_of[TOKENS * TOPK];
__device__ float g_wt[TOKENS * TOPK];
__device__ int   g_expert[TOKENS * TOPK];
__device__ int   g_cnt[NEXP];
__device__ int   g_cursor[NEXP];
__device__ int   g_off[NEXP + 1];

// ---------------- common PTX helpers ----------------
__device__ __forceinline__ uint32_t smem_u32(const void* p) {
    return (uint32_t)__cvta_generic_to_shared(p);
}
__device__ __forceinline__ void cp16(uint32_t dst, const void* src) {
    asm volatile("cp.async.cg.shared.global [%0], [%1], 16;" :: "r"(dst), "l"(src));
}
__device__ __forceinline__ void cp16z(uint32_t dst, const void* src) {
    asm volatile("cp.async.cg.shared.global [%0], [%1], 16, 0;" :: "r"(dst), "l"(src));
}
__device__ __forceinline__ void cp_commit() { asm volatile("cp.async.commit_group;"); }
__device__ __forceinline__ void cp_wait0()  { asm volatile("cp.async.wait_group 0;"); }
__device__ __forceinline__ void cp_wait1()  { asm volatile("cp.async.wait_group 1;"); }

__device__ __forceinline__ float tf32r(float x) {
    float r; asm("cvt.rna.tf32.f32 %0, %1;" : "=f"(r) : "f"(x)); return r;
}

// ---------------- small kernels ----------------
__global__ void k_zero() {
    int i = threadIdx.x;
    if (i < NEXP) { g_cnt[i] = 0; g_cursor[i] = 0; }
}

__global__ void k_route(const float* __restrict__ logits) {
    __shared__ int hist[NEXP];
    if (threadIdx.x < NEXP) hist[threadIdx.x] = 0;
    __syncthreads();

    int t = blockIdx.x * blockDim.x + threadIdx.x;
    if (t < TOKENS) {
        float l[NEXP];
#pragma unroll
        for (int i = 0; i < NEXP; i++) l[i] = logits[t * NEXP + i];
        float vals[TOPK]; int ids[TOPK];
#pragma unroll
        for (int k = 0; k < TOPK; k++) {
            float best = -INFINITY; int bi = 0;
#pragma unroll
            for (int i = 0; i < NEXP; i++)
                if (l[i] > best) { best = l[i]; bi = i; }
            vals[k] = best; ids[k] = bi; l[bi] = -INFINITY;
        }
        float m = vals[0], s = 0.f, ex[TOPK];
#pragma unroll
        for (int k = 0; k < TOPK; k++) { ex[k] = expf(vals[k] - m); s += ex[k]; }
        float inv = 1.f / s;
#pragma unroll
        for (int k = 0; k < TOPK; k++) {
            g_wt[t * TOPK + k] = ex[k] * inv;
            g_expert[t * TOPK + k] = ids[k];
            atomicAdd(&hist[ids[k]], 1);
        }
    }
    __syncthreads();
    if (threadIdx.x < NEXP && hist[threadIdx.x] > 0)
        atomicAdd(&g_cnt[threadIdx.x], hist[threadIdx.x]);
}

__global__ void k_scan() {
    if (threadIdx.x == 0) {
        int off = 0;
        for (int e = 0; e < NEXP; e++) {
            g_off[e] = off;
            off += ((g_cnt[e] + BM - 1) / BM) * BM;
        }
        g_off[NEXP] = off;
    }
}

__global__ void k_scatter() {
    int i = blockIdx.x * blockDim.x + threadIdx.x;
    if (i >= TOKENS * TOPK) return;
    int e = g_expert[i];
    int idx = atomicAdd(&g_cursor[e], 1);
    int slot = g_off[e] + idx;
    g_row_src[slot] = i / TOPK;
    g_slot_of[i] = slot;
}

__global__ void k_xround(const float* __restrict__ x) {
    size_t i = (size_t)blockIdx.x * blockDim.x + threadIdx.x;
    if (i >= (size_t)TOKENS * HID / 4) return;
    float4 v = ((const float4*)x)[i];
    v.x = tf32r(v.x); v.y = tf32r(v.y); v.z = tf32r(v.z); v.w = tf32r(v.w);
    ((float4*)g_xr)[i] = v;
}

// ---------------- weight prep: tf32-RN round + K-major SW128 tile bake ----------------
// gemm1 merged tile: rows 0..127 = gate n0..n0+127, rows 128..255 = up n0..n0+127,
// each row 32 k floats (128B), addr = n*128 + ((k*4)^((n&7)*16))
__global__ void __launch_bounds__(256) k_wprep1(const float* __restrict__ Wg,
                                                const float* __restrict__ Wu)
{
    int kc = blockIdx.x, nt = blockIdx.y, e = blockIdx.z;
    __shared__ float s[32][129];
    const float* srcs[2] = {
        Wg + (size_t)e * HID * INTER + (size_t)kc * 32 * INTER + nt * 128,
        Wu + (size_t)e * HID * INTER + (size_t)kc * 32 * INTER + nt * 128 };
    float* tile = g_wgu + (((size_t)e * NT1 + nt) * KT1 + kc) * 8192;

    for (int m = 0; m < 2; m++) {
        const float* src = srcs[m];
        float* dst = tile + m * 4096;   // gate at rows 0-127, up at rows 128-255
#pragma unroll
        for (int j = 0; j < 4; j++) {
            int idx = threadIdx.x + j * 256;
            int k = idx >> 5, c4 = idx & 31;
            float4 v = *(const float4*)(src + (size_t)k * INTER + c4 * 4);
            s[k][c4 * 4 + 0] = tf32r(v.x); s[k][c4 * 4 + 1] = tf32r(v.y);
            s[k][c4 * 4 + 2] = tf32r(v.z); s[k][c4 * 4 + 3] = tf32r(v.w);
        }
        __syncthreads();
#pragma unroll
        for (int j = 0; j < 4; j++) {
            int i = threadIdx.x + j * 256;
            int n = i >> 3, c = i & 7;
            float4 v = make_float4(s[c * 4 + 0][n], s[c * 4 + 1][n],
                                   s[c * 4 + 2][n], s[c * 4 + 3][n]);
            *(float4*)(dst + n * 32 + (((c * 16) ^ ((n & 7) * 16)) >> 2)) = v;
        }
        __syncthreads();
    }
}

__global__ void __launch_bounds__(256) k_wprep2(const float* __restrict__ Wd)
{
    int kc = blockIdx.x, nt = blockIdx.y, e = blockIdx.z;
    __shared__ float s[32][257];
    const float* src = Wd + (size_t)e * INTER * HID + (size_t)kc * 32 * HID + nt * 256;
    float* dst = g_wd + (((size_t)e * NT2 + nt) * KT2 + kc) * 8192;
#pragma unroll
    for (int j = 0; j < 8; j++) {
        int idx = threadIdx.x + j * 256;
        int k = idx >> 6, c4 = idx & 63;
        float4 v = *(const float4*)(src + (size_t)k * HID + c4 * 4);
        s[k][c4 * 4 + 0] = tf32r(v.x); s[k][c4 * 4 + 1] = tf32r(v.y);
        s[k][c4 * 4 + 2] = tf32r(v.z); s[k][c4 * 4 + 3] = tf32r(v.w);
    }
    __syncthreads();
#pragma unroll
    for (int j = 0; j < 8; j++) {
        int i = threadIdx.x + j * 256;
        int n = i >> 3, c = i & 7;
        float4 v = make_float4(s[c * 4 + 0][n], s[c * 4 + 1][n],
                               s[c * 4 + 2][n], s[c * 4 + 3][n]);
        *(float4*)(dst + n * 32 + (((c * 16) ^ ((n & 7) * 16)) >> 2)) = v;
    }
}

__global__ void k_combine(float* __restrict__ out) {
    int idx = blockIdx.x * blockDim.x + threadIdx.x;
    const int VPT = HID / 4;
    if (idx >= TOKENS * VPT) return;
    int t = idx / VPT;
    int c = (idx % VPT) * 4;
    float4 acc = make_float4(0.f, 0.f, 0.f, 0.f);
#pragma unroll
    for (int k = 0; k < TOPK; k++) {
        int slot = g_slot_of[t * TOPK + k];
        float w = g_wt[t * TOPK + k];
        float4 v = *(const float4*)(g_down + (size_t)slot * HID + c);
        acc.x += w * v.x; acc.y += w * v.y; acc.z += w * v.z; acc.w += w * v.w;
    }
    *(float4*)(out + (size_t)t * HID + c) = acc;
}

// ============================================================================
// tcgen05 path (bodies only in 'a' passes)
// ============================================================================
#if TC_OK
__device__ __forceinline__ uint32_t elect_one() {
    uint32_t p;
    asm volatile("{\n\t.reg .pred p;\n\telect.sync _|p, 0xFFFFFFFF;\n\tselp.b32 %0, 1, 0, p;\n\t}" : "=r"(p));
    return p;
}

#define MBAR_INIT(addr, cnt) \
    asm volatile("mbarrier.init.shared.b64 [%0], %1;" :: "r"(addr), "r"(cnt) : "memory")
#define MBAR_WAIT(addr, parity) do { \
    uint32_t _m = (addr), _p = (parity); \
    asm volatile("{\n\t.reg .pred P;\n\tWL_%=:\n\t" \
        "mbarrier.try_wait.parity.acquire.cta.shared::cta.b64 P, [%0], %1, 0x989680;\n\t" \
        "@P bra.uni WD_%=;\n\tbra.uni WL_%=;\n\tWD_%=:\n\t}" \
        :: "r"(_m), "r"(_p) : "memory"); } while (0)

#define TC_ALLOC(dst, n)  asm volatile("tcgen05.alloc.cta_group::1.sync.aligned.shared::cta.b32 [%0], %1;" :: "r"(dst), "r"(n) : "memory")
#define TC_DEALLOC(t, n)  asm volatile("tcgen05.dealloc.cta_group::1.sync.aligned.b32 %0, %1;" :: "r"(t), "r"(n))
#define TC_RELINQ()       asm volatile("tcgen05.relinquish_alloc_permit.cta_group::1.sync.aligned;")
#define TC_COMMIT(mb)     asm volatile("tcgen05.commit.cta_group::1.mbarrier::arrive::one.shared::cluster.b64 [%0];" :: "r"(mb) : "memory")
#define TC_FENCE_AFTER()  asm volatile("tcgen05.fence::after_thread_sync;" ::: "memory")
#define TC_FENCE_BEFORE() asm volatile("tcgen05.fence::before_thread_sync;" ::: "memory")
#define TC_WAIT_LD()      asm volatile("tcgen05.wait::ld.sync.aligned;" ::: "memory")
#define FENCE_ASYNC()     asm volatile("fence.proxy.async.shared::cta;" ::: "memory")

#define TC_LD_X16(r, addr) \
    asm volatile("tcgen05.ld.sync.aligned.32x32b.x16.b32 " \
        "{%0,%1,%2,%3,%4,%5,%6,%7,%8,%9,%10,%11,%12,%13,%14,%15}, [%16];" \
        : "=r"((r)[0]), "=r"((r)[1]), "=r"((r)[2]), "=r"((r)[3]), \
          "=r"((r)[4]), "=r"((r)[5]), "=r"((r)[6]), "=r"((r)[7]), \
          "=r"((r)[8]), "=r"((r)[9]), "=r"((r)[10]), "=r"((r)[11]), \
          "=r"((r)[12]), "=r"((r)[13]), "=r"((r)[14]), "=r"((r)[15]) \
        : "r"(addr))

#define TC_LD_X32(r, addr) \
    asm volatile("tcgen05.ld.sync.aligned.32x32b.x32.b32 " \
        "{%0,%1,%2,%3,%4,%5,%6,%7,%8,%9,%10,%11,%12,%13,%14,%15," \
        "%16,%17,%18,%19,%20,%21,%22,%23,%24,%25,%26,%27,%28,%29,%30,%31}, [%32];" \
        : "=r"((r)[0]), "=r"((r)[1]), "=r"((r)[2]), "=r"((r)[3]), \
          "=r"((r)[4]), "=r"((r)[5]), "=r"((r)[6]), "=r"((r)[7]), \
          "=r"((r)[8]), "=r"((r)[9]), "=r"((r)[10]), "=r"((r)[11]), \
          "=r"((r)[12]), "=r"((r)[13]), "=r"((r)[14]), "=r"((r)[15]), \
          "=r"((r)[16]), "=r"((r)[17]), "=r"((r)[18]), "=r"((r)[19]), \
          "=r"((r)[20]), "=r"((r)[21]), "=r"((r)[22]), "=r"((r)[23]), \
          "=r"((r)[24]), "=r"((r)[25]), "=r"((r)[26]), "=r"((r)[27]), \
          "=r"((r)[28]), "=r"((r)[29]), "=r"((r)[30]), "=r"((r)[31]) \
        : "r"(addr))

__device__ __forceinline__ void mma_tf32(uint32_t d_tmem, uint64_t a_desc, uint64_t b_desc,
                                         uint32_t idesc, bool acc) {
    uint32_t en = acc ? 1u : 0u;
    asm volatile("{\n\t.reg .pred p;\n\tsetp.ne.u32 p, %5, 0;\n\t"
                 "tcgen05.mma.cta_group::1.kind::tf32 [%0], %1, %2, %3, {%4, %4, %4, %4}, p;\n\t}"
                 :: "r"(d_tmem), "l"(a_desc), "l"(b_desc), "r"(idesc), "r"(0u), "r"(en)
                 : "memory");
}

__device__ __forceinline__ uint64_t mkdesc(uint32_t addr) {
    const uint64_t base = (2ull << 61) | (1ull << 46) | (64ull << 32) | (1ull << 16);
    return base | ((uint64_t)(addr >> 4) & 0x3FFF);
}

#define IDESC_N128 ((1u << 4) | (2u << 7) | (2u << 10) | (16u << 17) | (8u << 24))
#endif  // TC_OK

// ---------------- GEMM1 tcgen05: gate+up, M=256, 4x N=128 dispatches, BK=32, 3-stage ----------------
// TMEM: [0:128)=D0 gate, [128:256)=D0 up, [256:384)=D1 gate, [384:512)=D1 up
__global__ void __launch_bounds__(256, 1) k_gemm1_tc(const float* __restrict__ WgU,
                                                     const float* __restrict__ WuU)
{
#if TC_OK
    int e = blockIdx.z;
    int cnt = g_cnt[e];
    int mpair = blockIdx.x;
    if (mpair * 256 >= cnt) return;
    int base = g_off[e];
    int ntiles = (cnt + 127) >> 7;
    int nt = blockIdx.y;
    int n0 = nt * 128;

    extern __shared__ char dsm[];
    __shared__ uint32_t s_tmem;
    __shared__ uint64_t s_mbar[3];
    uint32_t sbase = (smem_u32(dsm) + 1023) & ~1023u;
    // per stage (64KB): A0 @0, A1 @16K, B merged [gate|up] @32K (32KB)
    uint32_t stg[3] = { sbase, sbase + 65536, sbase + 131072 };

    int tid = threadIdx.x, wid = tid >> 5, lane = tid & 31;

    if (tid == 0) {
        MBAR_INIT(smem_u32(&s_mbar[0]), 1);
        MBAR_INIT(smem_u32(&s_mbar[1]), 1);
        MBAR_INIT(smem_u32(&s_mbar[2]), 1);
    }
    if (wid == 0) { TC_ALLOC(smem_u32(&s_tmem), 512); TC_RELINQ(); }
    __syncthreads();
    uint32_t tmem = s_tmem;

    // A gather map: 8 rows per thread across 256 rows
    int c8 = tid & 7;
    const float* asrc[8];
    uint32_t adst[8];
#pragma unroll
    for (int p = 0; p < 8; p++) {
        int r = (tid >> 3) + p * 32;            // 0..255
        int gr = mpair * 256 + r;
        int s = (gr < cnt) ? g_row_src[base + gr] : -1;
        asrc[p] = (s >= 0) ? (g_xr + (size_t)s * HID + c8 * 4) : nullptr;
        int lr = r & 127;
        adst[p] = (uint32_t)((r >> 7) * 16384 + lr * 128 + ((c8 ^ (lr & 7)) * 16));
    }

    // merged B tile stream: 8192 floats (32KB) per k-chunk, 8 float4 per thread
    const float* tb = g_wgu + (((size_t)e * NT1 + nt) * KT1) * 8192 + tid * 32;
    uint32_t bdst = (uint32_t)(tid * 128);

    auto load_stage = [&](uint32_t bb, int it) {
        int k0 = it * 32;
#pragma unroll
        for (int p = 0; p < 8; p++) {
            if (asrc[p]) cp16(bb + adst[p], asrc[p] + k0);
            else         cp16z(bb + adst[p], g_xr);
        }
        const float* pb = tb + (size_t)it * 8192;
#pragma unroll
        for (int j = 0; j < 8; j++)
            cp16(bb + 32768 + bdst + j * 16, pb + j * 4);
        cp_commit();
    };

    const int KT = KT1;   // 64
    int ph[3] = { 0, 0, 0 };

    load_stage(stg[0], 0);
    load_stage(stg[1], 1);

    for (int it = 0; it < KT; it++) {
        int s = it % 3;
        uint32_t bb = stg[s];
        // Last iteration has only ONE group in flight — drain fully there.
        if (it == KT - 1) cp_wait0(); else cp_wait1();
        __syncthreads();

        if (wid == 0) {
            FENCE_ASYNC();
            if (elect_one()) {
                uint64_t da0 = mkdesc(bb);
                uint64_t da1 = mkdesc(bb + 16384);
                uint64_t dbg = mkdesc(bb + 32768);           // gate rows 0-127
                uint64_t dbu = mkdesc(bb + 32768 + 16384);   // up rows 128-255
#pragma unroll
                for (int ks = 0; ks < 4; ks++) {
                    bool acc = !(it == 0 && ks == 0);
                    mma_tf32(tmem,       da0 + 2 * ks, dbg + 2 * ks, IDESC_N128, acc);
                    mma_tf32(tmem + 128, da0 + 2 * ks, dbu + 2 * ks, IDESC_N128, acc);
                    mma_tf32(tmem + 256, da1 + 2 * ks, dbg + 2 * ks, IDESC_N128, acc);
                    mma_tf32(tmem + 384, da1 + 2 * ks, dbu + 2 * ks, IDESC_N128, acc);
                }
                TC_COMMIT(smem_u32(&s_mbar[s]));
            }
        }

        int nx = it + 2;
        if (nx < KT) {
            int sn = nx % 3;     // == (it-1)%3 for it>=1
            if (it >= 1) { MBAR_WAIT(smem_u32(&s_mbar[sn]), ph[sn]); ph[sn] ^= 1; }
            load_stage(stg[sn], nx);
        }
    }

    int ls = (KT - 1) % 3;
    MBAR_WAIT(smem_u32(&s_mbar[ls]), ph[ls]);
    TC_FENCE_AFTER();

    if (wid < 4) {
        int m = wid * 32 + lane;
#pragma unroll
        for (int t = 0; t < 2; t++) {
            int mt = mpair * 2 + t;
            if (mt >= ntiles) break;
            float* dst = g_h + (size_t)(base + mt * 128 + m) * INTER + n0;
#pragma unroll
            for (int c0 = 0; c0 < 128; c0 += 16) {
                uint32_t rg[16], ru[16];
                TC_LD_X16(rg, tmem + t * 256 + c0);          // gate cols
                TC_LD_X16(ru, tmem + t * 256 + 128 + c0);    // up cols
                TC_WAIT_LD();
#pragma unroll
                for (int j = 0; j < 16; j++) {
                    float g = __uint_as_float(rg[j]);
                    float u = __uint_as_float(ru[j]);
                    float h = (g / (1.f + __expf(-g))) * u;
                    rg[j] = __float_as_uint(tf32r(h));
                }
#pragma unroll
                for (int j = 0; j < 16; j += 4)
                    *(uint4*)(dst + c0 + j) = make_uint4(rg[j], rg[j+1], rg[j+2], rg[j+3]);
            }
        }
        TC_FENCE_BEFORE();
    }
    __syncthreads();
    if (wid == 0) TC_DEALLOC(tmem, 512);
#endif
}

// ---------------- GEMM2 tcgen05: down, M=256, 4x N=128 dispatches, BK=32, 3-stage ----------------
// TMEM: [0:128)=D0 n-lo, [128:256)=D0 n-hi, [256:384)=D1 n-lo, [384:512)=D1 n-hi
__global__ void __launch_bounds__(256, 1) k_gemm2_tc(const float* __restrict__ WdU)
{
#if TC_OK
    int e = blockIdx.z;
    int cnt = g_cnt[e];
    int mpair = blockIdx.x;
    if (mpair * 256 >= cnt) return;
    int base = g_off[e];
    int ntiles = (cnt + 127) >> 7;
    int nt = blockIdx.y;
    int n0 = nt * 256;

    extern __shared__ char dsm[];
    __shared__ uint32_t s_tmem;
    __shared__ uint64_t s_mbar[3];
    uint32_t sbase = (smem_u32(dsm) + 1023) & ~1023u;
    uint32_t stg[3] = { sbase, sbase + 65536, sbase + 131072 };

    int tid = threadIdx.x, wid = tid >> 5, lane = tid & 31;

    if (tid == 0) {
        MBAR_INIT(smem_u32(&s_mbar[0]), 1);
        MBAR_INIT(smem_u32(&s_mbar[1]), 1);
        MBAR_INIT(smem_u32(&s_mbar[2]), 1);
    }
    if (wid == 0) { TC_ALLOC(smem_u32(&s_tmem), 512); TC_RELINQ(); }
    __syncthreads();
    uint32_t tmem = s_tmem;

    int c8 = tid & 7;
    const float* asrc[8];
    uint32_t adst[8];
#pragma unroll
    for (int p = 0; p < 8; p++) {
        int r = (tid >> 3) + p * 32;
        asrc[p] = g_h + (size_t)(base + mpair * 256 + r) * INTER + c8 * 4;
        int lr = r & 127;
        adst[p] = (uint32_t)((r >> 7) * 16384 + lr * 128 + ((c8 ^ (lr & 7)) * 16));
    }

    const float* td = g_wd + (((size_t)e * NT2 + nt) * KT2) * 8192 + tid * 32;
    uint32_t bdst = (uint32_t)(tid * 128);

    auto load_stage = [&](uint32_t bb, int it) {
        int k0 = it * 32;
#pragma unroll
        for (int p = 0; p < 8; p++)
            cp16(bb + adst[p], asrc[p] + k0);
        const float* pw = td + (size_t)it * 8192;
#pragma unroll
        for (int j = 0; j < 8; j++)
            cp16(bb + 32768 + bdst + j * 16, pw + j * 4);
        cp_commit();
    };

    const int KT = KT2;   // 24
    int ph[3] = { 0, 0, 0 };

    load_stage(stg[0], 0);
    load_stage(stg[1], 1);

    for (int it = 0; it < KT; it++) {
        int s = it % 3;
        uint32_t bb = stg[s];
        if (it == KT - 1) cp_wait0(); else cp_wait1();
        __syncthreads();

        if (wid == 0) {
            FENCE_ASYNC();
            if (elect_one()) {
                uint64_t da0 = mkdesc(bb);
                uint64_t da1 = mkdesc(bb + 16384);
                uint64_t db0 = mkdesc(bb + 32768);           // n rows 0-127
                uint64_t db1 = mkdesc(bb + 32768 + 16384);   // n rows 128-255
#pragma unroll
                for (int ks = 0; ks < 4; ks++) {
                    bool acc = !(it == 0 && ks == 0);
                    mma_tf32(tmem,       da0 + 2 * ks, db0 + 2 * ks, IDESC_N128, acc);
                    mma_tf32(tmem + 128, da0 + 2 * ks, db1 + 2 * ks, IDESC_N128, acc);
                    mma_tf32(tmem + 256, da1 + 2 * ks, db0 + 2 * ks, IDESC_N128, acc);
                    mma_tf32(tmem + 384, da1 + 2 * ks, db1 + 2 * ks, IDESC_N128, acc);
                }
                TC_COMMIT(smem_u32(&s_mbar[s]));
            }
        }

        int nx = it + 2;
        if (nx < KT) {
            int sn = nx % 3;
            if (it >= 1) { MBAR_WAIT(smem_u32(&s_mbar[sn]), ph[sn]); ph[sn] ^= 1; }
            load_stage(stg[sn], nx);
        }
    }

    int ls = (KT - 1) % 3;
    MBAR_WAIT(smem_u32(&s_mbar[ls]), ph[ls]);
    TC_FENCE_AFTER();

    if (wid < 4) {
        int m = wid * 32 + lane;
#pragma unroll
        for (int t = 0; t < 2; t++) {
            int mt = mpair * 2 + t;
            if (mt >= ntiles) break;
            float* dst = g_down + (size_t)(base + mt * 128 + m) * HID + n0;
#pragma unroll
            for (int c0 = 0; c0 < 256; c0 += 32) {
                uint32_t r[32];
                TC_LD_X32(r, tmem + t * 256 + c0);
                TC_WAIT_LD();
#pragma unroll
                for (int j = 0; j < 32; j += 4)
                    *(uint4*)(dst + c0 + j) = make_uint4(r[j], r[j+1], r[j+2], r[j+3]);
            }
        }
        TC_FENCE_BEFORE();
    }
    __syncthreads();
    if (wid == 0) TC_DEALLOC(tmem, 512);
#endif
}

// ============================================================================
// wmma fallback path (bodies only in non-'a' device passes; reads raw weights)
// ============================================================================
#define FBK 16

__global__ void __launch_bounds__(256) k_gemm1_wm(
    const float* __restrict__ x,
    const float* __restrict__ Wg,
    const float* __restrict__ Wu)
{
#if !TC_OK
    int e = blockIdx.z;
    int cnt = g_cnt[e];
    if ((int)blockIdx.x * BM >= cnt) return;
    int base = g_off[e];
    int n0 = blockIdx.y * 64;

    __shared__ float sA [2][BM][FBK + 4];
    __shared__ float sBg[2][FBK][64 + 4];
    __shared__ float sBu[2][FBK][64 + 4];

    int tid = threadIdx.x;
    int wid = tid >> 5;
    int wm = wid >> 1;
    int wn = wid & 1;

    int arow = tid >> 2;
    int acol = (tid & 3) << 2;
    const float* aptr[2];
#pragma unroll
    for (int p = 0; p < 2; p++) {
        int r = blockIdx.x * BM + p * 64 + arow;
        int s = (r < cnt) ? g_row_src[base + r] : -1;
        aptr[p] = (s >= 0) ? (x + (size_t)s * HID + acol) : nullptr;
    }
    int brow = tid >> 4;
    int bcol = (tid & 15) << 2;
    const float* bg = Wg + (size_t)e * HID * INTER + (size_t)brow * INTER + n0 + bcol;
    const float* bu = Wu + (size_t)e * HID * INTER + (size_t)brow * INTER + n0 + bcol;

    wmma::fragment<wmma::accumulator, 16, 16, 8, float> accG[2][2], accU[2][2];
#pragma unroll
    for (int im = 0; im < 2; im++)
#pragma unroll
        for (int in = 0; in < 2; in++) {
            wmma::fill_fragment(accG[im][in], 0.f);
            wmma::fill_fragment(accU[im][in], 0.f);
        }

    auto load_tile = [&](int buf, int k0) {
#pragma unroll
        for (int p = 0; p < 2; p++) {
            uint32_t d = smem_u32(&sA[buf][p * 64 + arow][acol]);
            if (aptr[p]) cp16(d, aptr[p] + k0);
            else         cp16z(d, x);
        }
        cp16(smem_u32(&sBg[buf][brow][bcol]), bg + (size_t)k0 * INTER);
        cp16(smem_u32(&sBu[buf][brow][bcol]), bu + (size_t)k0 * INTER);
    };

    load_tile(0, 0);
    cp_commit();

    int buf = 0;
    for (int k0 = 0; k0 < HID; k0 += FBK) {
        cp_wait0();
        __syncthreads();
        if (k0 + FBK < HID) { load_tile(buf ^ 1, k0 + FBK); cp_commit(); }

#pragma unroll
        for (int kk = 0; kk < FBK; kk += 8) {
            wmma::fragment<wmma::matrix_a, 16, 16, 8, wmma::precision::tf32, wmma::row_major> a[2];
            wmma::fragment<wmma::matrix_b, 16, 16, 8, wmma::precision::tf32, wmma::row_major> fg[2], fu[2];
#pragma unroll
            for (int im = 0; im < 2; im++) {
                wmma::load_matrix_sync(a[im], &sA[buf][wm * 32 + im * 16][kk], FBK + 4);
#pragma unroll
                for (int i = 0; i < a[im].num_elements; i++)
                    a[im].x[i] = wmma::__float_to_tf32(a[im].x[i]);
            }
#pragma unroll
            for (int in = 0; in < 2; in++) {
                wmma::load_matrix_sync(fg[in], &sBg[buf][kk][wn * 32 + in * 16], 64 + 4);
                wmma::load_matrix_sync(fu[in], &sBu[buf][kk][wn * 32 + in * 16], 64 + 4);
#pragma unroll
                for (int i = 0; i < fg[in].num_elements; i++) {
                    fg[in].x[i] = wmma::__float_to_tf32(fg[in].x[i]);
                    fu[in].x[i] = wmma::__float_to_tf32(fu[in].x[i]);
                }
            }
#pragma unroll
            for (int im = 0; im < 2; im++)
#pragma unroll
                for (int in = 0; in < 2; in++) {
                    wmma::mma_sync(accG[im][in], a[im], fg[in], accG[im][in]);
                    wmma::mma_sync(accU[im][in], a[im], fu[in], accU[im][in]);
                }
        }
        buf ^= 1;
    }

#pragma unroll
    for (int im = 0; im < 2; im++)
#pragma unroll
        for (int in = 0; in < 2; in++) {
#pragma unroll
            for (int i = 0; i < accG[im][in].num_elements; i++) {
                float g = accG[im][in].x[i];
                float u = accU[im][in].x[i];
                accG[im][in].x[i] = (g / (1.f + expf(-g))) * u;
            }
            size_t row = (size_t)base + blockIdx.x * BM + wm * 32 + im * 16;
            wmma::store_matrix_sync(g_h + row * INTER + n0 + wn * 32 + in * 16,
                                    accG[im][in], INTER, wmma::mem_row_major);
        }
#endif
}

__global__ void __launch_bounds__(256) k_gemm2_wm(const float* __restrict__ Wd)
{
#if !TC_OK
    int e = blockIdx.z;
    int cnt = g_cnt[e];
    if ((int)blockIdx.x * BM >= cnt) return;
    int base = g_off[e];
    int n0 = blockIdx.y * 64;

    __shared__ float sA[2][BM][FBK + 4];
    __shared__ float sB[2][FBK][64 + 4];

    int tid = threadIdx.x;
    int wid = tid >> 5;
    int wm = wid >> 1;
    int wn = wid & 1;

    int arow = tid >> 2;
    int acol = (tid & 3) << 2;
    const float* A = g_h + (size_t)(base + blockIdx.x * BM) * INTER;

    int brow = tid >> 4;
    int bcol = (tid & 15) << 2;
    const float* B = Wd + (size_t)e * INTER * HID + (size_t)brow * HID + n0 + bcol;

    wmma::fragment<wmma::accumulator, 16, 16, 8, float> acc[2][2];
#pragma unroll
    for (int im = 0; im < 2; im++)
#pragma unroll
        for (int in = 0; in < 2; in++)
            wmma::fill_fragment(acc[im][in], 0.f);

    auto load_tile = [&](int buf, int k0) {
#pragma unroll
        for (int p = 0; p < 2; p++) {
            int r = p * 64 + arow;
            cp16(smem_u32(&sA[buf][r][acol]), A + (size_t)r * INTER + k0 + acol);
        }
        cp16(smem_u32(&sB[buf][brow][bcol]), B + (size_t)k0 * HID);
    };

    load_tile(0, 0);
    cp_commit();

    int buf = 0;
    for (int k0 = 0; k0 < INTER; k0 += FBK) {
        cp_wait0();
        __syncthreads();
        if (k0 + FBK < INTER) { load_tile(buf ^ 1, k0 + FBK); cp_commit(); }

#pragma unroll
        for (int kk = 0; kk < FBK; kk += 8) {
            wmma::fragment<wmma::matrix_a, 16, 16, 8, wmma::precision::tf32, wmma::row_major> a[2];
            wmma::fragment<wmma::matrix_b, 16, 16, 8, wmma::precision::tf32, wmma::row_major> b[2];
#pragma unroll
            for (int im = 0; im < 2; im++) {
                wmma::load_matrix_sync(a[im], &sA[buf][wm * 32 + im * 16][kk], FBK + 4);
#pragma unroll
                for (int i = 0; i < a[im].num_elements; i++)
                    a[im].x[i] = wmma::__float_to_tf32(a[im].x[i]);
            }
#pragma unroll
            for (int in = 0; in < 2; in++) {
                wmma::load_matrix_sync(b[in], &sB[buf][kk][wn * 32 + in * 16], 64 + 4);
#pragma unroll
                for (int i = 0; i < b[in].num_elements; i++)
                    b[in].x[i] = wmma::__float_to_tf32(b[in].x[i]);
            }
#pragma unroll
            for (int im = 0; im < 2; im++)
#pragma unroll
                for (int in = 0; in < 2; in++)
                    wmma::mma_sync(acc[im][in], a[im], b[in], acc[im][in]);
        }
        buf ^= 1;
    }

#pragma unroll
    for (int im = 0; im < 2; im++)
#pragma unroll
        for (int in = 0; in < 2; in++) {
            size_t row = (size_t)base + blockIdx.x * BM + wm * 32 + im * 16;
            wmma::store_matrix_sync(g_down + row * HID + n0 + wn * 32 + in * 16,
                                    acc[im][in], HID, wmma::mem_row_major);
        }
#endif
}

// ---------------- launch ----------------
extern "C" void kernel_launch(void* const* d_in, const int* in_sizes, int n_in,
                              void* d_out, int out_size)
{
    const float* x      = (const float*)d_in[0];
    const float* logits = (const float*)d_in[1];
    const float* Wg     = (const float*)d_in[2];
    const float* Wu     = (const float*)d_in[3];
    const float* Wd     = (const float*)d_in[4];
    float* out = (float*)d_out;

    cudaFuncSetAttribute(k_gemm1_tc, cudaFuncAttributeMaxDynamicSharedMemorySize, 197632);
    cudaFuncSetAttribute(k_gemm2_tc, cudaFuncAttributeMaxDynamicSharedMemorySize, 197632);

    k_zero<<<1, 64>>>();
    k_route<<<(TOKENS + 127) / 128, 128>>>(logits);
    k_scan<<<1, 32>>>();
    k_scatter<<<(TOKENS * TOPK + 255) / 256, 256>>>();
    k_xround<<<(TOKENS * HID / 4 + 255) / 256, 256>>>(x);

    // weight prep: tf32-RN round + K-major SW128 tile bake
    dim3 gp1(KT1, NT1, NEXP);
    k_wprep1<<<gp1, 256>>>(Wg, Wu);
    dim3 gp2(KT2, NT2, NEXP);
    k_wprep2<<<gp2, 256>>>(Wd);

    // tcgen05 path (no-op in non-'a' cubins)
    dim3 g1t(MP_MAX, NT1, NEXP);
    k_gemm1_tc<<<g1t, 256, 197632>>>(Wg, Wu);
    dim3 g2t(MP_MAX, NT2, NEXP);
    k_gemm2_tc<<<g2t, 256, 197632>>>(Wd);

    // wmma fallback path (no-op in 'a' cubins)
    dim3 g1w(TOKENS / BM, INTER / 64, NEXP);
    k_gemm1_wm<<<g1w, 256>>>(x, Wg, Wu);
    dim3 g2w(TOKENS / BM, HID / 64, NEXP);
    k_gemm2_wm<<<g2w, 256>>>(Wd);

    int tot = TOKENS * (HID / 4);
    k_combine<<<(tot + 255) / 256, 256>>>(out);
}

// round 17
// speedup vs baseline: 1.6353x; 1.1640x over previous
#include <cuda_runtime.h>
#include <mma.h>
#include <math.h>
#include <stdint.h>

using namespace nvcuda;

// tcgen05 is only legal in arch-accelerated ('a') compile passes.
#if defined(__CUDA_ARCH_FEAT_SM103_ALL) || defined(__CUDA_ARCH_FEAT_SM100_ALL) || defined(__CUDA_ARCH_FEAT_SM101_ALL)
#define TC_OK 1
#else
#define TC_OK 0
#endif

#define TOKENS 8192
#define NEXP   64
#define TOPK   8
#define HID    2048
#define INTER  768
#define BM     128
#define MP_MAX 12      // m-pairs per expert

#define NT1 6      // gemm1 n-tiles (INTER/128)
#define KT1 64     // gemm1 k-chunks (HID/32)
#define NT2 8      // gemm2 n-tiles (HID/256)
#define KT2 24     // gemm2 k-chunks (INTER/32)

#define MAXROWS (TOKENS * TOPK + NEXP * 256)   // pair-tail slack

// ---------------- scratch (static device memory) ----------------
__device__ float g_xr[(size_t)TOKENS * HID];       // tf32-rounded X
__device__ float g_h[(size_t)MAXROWS * INTER];     // silu(gate)*up
__device__ float g_down[(size_t)MAXROWS * HID];
// pre-rounded + pre-swizzled weight tile images (SW128 K-major)
__device__ float g_wg[(size_t)NEXP * NT1 * KT1 * 4096];
__device__ float g_wu[(size_t)NEXP * NT1 * KT1 * 4096];
__device__ float g_wd[(size_t)NEXP * NT2 * KT2 * 8192];
__device__ int   g_row_src[MAXROWS];
__device__ int   g_slot_of[TOKENS * TOPK];
__device__ float g_wt[TOKENS * TOPK];
__device__ int   g_expert[TOKENS * TOPK];
__device__ int   g_cnt[NEXP];
__device__ int   g_cursor[NEXP];
__device__ int   g_off[NEXP + 1];

// ---------------- common PTX helpers ----------------
__device__ __forceinline__ uint32_t smem_u32(const void* p) {
    return (uint32_t)__cvta_generic_to_shared(p);
}
__device__ __forceinline__ void cp16(uint32_t dst, const void* src) {
    asm volatile("cp.async.cg.shared.global [%0], [%1], 16;" :: "r"(dst), "l"(src));
}
__device__ __forceinline__ void cp16z(uint32_t dst, const void* src) {
    asm volatile("cp.async.cg.shared.global [%0], [%1], 16, 0;" :: "r"(dst), "l"(src));
}
__device__ __forceinline__ void cp_commit() { asm volatile("cp.async.commit_group;"); }
__device__ __forceinline__ void cp_wait0()  { asm volatile("cp.async.wait_group 0;"); }
__device__ __forceinline__ void cp_wait1()  { asm volatile("cp.async.wait_group 1;"); }

__device__ __forceinline__ float tf32r(float x) {
    float r; asm("cvt.rna.tf32.f32 %0, %1;" : "=f"(r) : "f"(x)); return r;
}

// ---------------- small kernels ----------------
__global__ void k_zero() {
    int i = threadIdx.x;
    if (i < NEXP) { g_cnt[i] = 0; g_cursor[i] = 0; }
}

__global__ void k_route(const float* __restrict__ logits) {
    __shared__ int hist[NEXP];
    if (threadIdx.x < NEXP) hist[threadIdx.x] = 0;
    __syncthreads();

    int t = blockIdx.x * blockDim.x + threadIdx.x;
    if (t < TOKENS) {
        float l[NEXP];
#pragma unroll
        for (int i = 0; i < NEXP; i++) l[i] = logits[t * NEXP + i];
        float vals[TOPK]; int ids[TOPK];
#pragma unroll
        for (int k = 0; k < TOPK; k++) {
            float best = -INFINITY; int bi = 0;
#pragma unroll
            for (int i = 0; i < NEXP; i++)
                if (l[i] > best) { best = l[i]; bi = i; }
            vals[k] = best; ids[k] = bi; l[bi] = -INFINITY;
        }
        float m = vals[0], s = 0.f, ex[TOPK];
#pragma unroll
        for (int k = 0; k < TOPK; k++) { ex[k] = expf(vals[k] - m); s += ex[k]; }
        float inv = 1.f / s;
#pragma unroll
        for (int k = 0; k < TOPK; k++) {
            g_wt[t * TOPK + k] = ex[k] * inv;
            g_expert[t * TOPK + k] = ids[k];
            atomicAdd(&hist[ids[k]], 1);
        }
    }
    __syncthreads();
    if (threadIdx.x < NEXP && hist[threadIdx.x] > 0)
        atomicAdd(&g_cnt[threadIdx.x], hist[threadIdx.x]);
}

__global__ void k_scan() {
    if (threadIdx.x == 0) {
        int off = 0;
        for (int e = 0; e < NEXP; e++) {
            g_off[e] = off;
            off += ((g_cnt[e] + BM - 1) / BM) * BM;
        }
        g_off[NEXP] = off;
    }
}

__global__ void k_scatter() {
    int i = blockIdx.x * blockDim.x + threadIdx.x;
    if (i >= TOKENS * TOPK) return;
    int e = g_expert[i];
    int idx = atomicAdd(&g_cursor[e], 1);
    int slot = g_off[e] + idx;
    g_row_src[slot] = i / TOPK;
    g_slot_of[i] = slot;
}

__global__ void k_xround(const float* __restrict__ x) {
    size_t i = (size_t)blockIdx.x * blockDim.x + threadIdx.x;
    if (i >= (size_t)TOKENS * HID / 4) return;
    float4 v = ((const float4*)x)[i];
    v.x = tf32r(v.x); v.y = tf32r(v.y); v.z = tf32r(v.z); v.w = tf32r(v.w);
    ((float4*)g_xr)[i] = v;
}

// ---------------- weight prep: tf32-RN round + K-major SW128 tile bake ----------------
__global__ void __launch_bounds__(256) k_wprep1(const float* __restrict__ Wg,
                                                const float* __restrict__ Wu)
{
    int kc = blockIdx.x, nt = blockIdx.y, e = blockIdx.z;
    __shared__ float s[32][129];
    const float* srcs[2] = {
        Wg + (size_t)e * HID * INTER + (size_t)kc * 32 * INTER + nt * 128,
        Wu + (size_t)e * HID * INTER + (size_t)kc * 32 * INTER + nt * 128 };
    float* dsts[2] = {
        g_wg + (((size_t)e * NT1 + nt) * KT1 + kc) * 4096,
        g_wu + (((size_t)e * NT1 + nt) * KT1 + kc) * 4096 };

    for (int m = 0; m < 2; m++) {
        const float* src = srcs[m];
        float* dst = dsts[m];
#pragma unroll
        for (int j = 0; j < 4; j++) {
            int idx = threadIdx.x + j * 256;
            int k = idx >> 5, c4 = idx & 31;
            float4 v = *(const float4*)(src + (size_t)k * INTER + c4 * 4);
            s[k][c4 * 4 + 0] = tf32r(v.x); s[k][c4 * 4 + 1] = tf32r(v.y);
            s[k][c4 * 4 + 2] = tf32r(v.z); s[k][c4 * 4 + 3] = tf32r(v.w);
        }
        __syncthreads();
#pragma unroll
        for (int j = 0; j < 4; j++) {
            int i = threadIdx.x + j * 256;
            int n = i >> 3, c = i & 7;
            float4 v = make_float4(s[c * 4 + 0][n], s[c * 4 + 1][n],
                                   s[c * 4 + 2][n], s[c * 4 + 3][n]);
            *(float4*)(dst + n * 32 + (((c * 16) ^ ((n & 7) * 16)) >> 2)) = v;
        }
        __syncthreads();
    }
}

__global__ void __launch_bounds__(256) k_wprep2(const float* __restrict__ Wd)
{
    int kc = blockIdx.x, nt = blockIdx.y, e = blockIdx.z;
    __shared__ float s[32][257];
    const float* src = Wd + (size_t)e * INTER * HID + (size_t)kc * 32 * HID + nt * 256;
    float* dst = g_wd + (((size_t)e * NT2 + nt) * KT2 + kc) * 8192;
#pragma unroll
    for (int j = 0; j < 8; j++) {
        int idx = threadIdx.x + j * 256;
        int k = idx >> 6, c4 = idx & 63;
        float4 v = *(const float4*)(src + (size_t)k * HID + c4 * 4);
        s[k][c4 * 4 + 0] = tf32r(v.x); s[k][c4 * 4 + 1] = tf32r(v.y);
        s[k][c4 * 4 + 2] = tf32r(v.z); s[k][c4 * 4 + 3] = tf32r(v.w);
    }
    __syncthreads();
#pragma unroll
    for (int j = 0; j < 8; j++) {
        int i = threadIdx.x + j * 256;
        int n = i >> 3, c = i & 7;
        float4 v = make_float4(s[c * 4 + 0][n], s[c * 4 + 1][n],
                               s[c * 4 + 2][n], s[c * 4 + 3][n]);
        *(float4*)(dst + n * 32 + (((c * 16) ^ ((n & 7) * 16)) >> 2)) = v;
    }
}

__global__ void k_combine(float* __restrict__ out) {
    int idx = blockIdx.x * blockDim.x + threadIdx.x;
    const int VPT = HID / 4;
    if (idx >= TOKENS * VPT) return;
    int t = idx / VPT;
    int c = (idx % VPT) * 4;
    float4 acc = make_float4(0.f, 0.f, 0.f, 0.f);
#pragma unroll
    for (int k = 0; k < TOPK; k++) {
        int slot = g_slot_of[t * TOPK + k];
        float w = g_wt[t * TOPK + k];
        float4 v = *(const float4*)(g_down + (size_t)slot * HID + c);
        acc.x += w * v.x; acc.y += w * v.y; acc.z += w * v.z; acc.w += w * v.w;
    }
    *(float4*)(out + (size_t)t * HID + c) = acc;
}

// ============================================================================
// tcgen05 path (bodies only in 'a' passes)
// ============================================================================
#if TC_OK
__device__ __forceinline__ uint32_t elect_one() {
    uint32_t p;
    asm volatile("{\n\t.reg .pred p;\n\telect.sync _|p, 0xFFFFFFFF;\n\tselp.b32 %0, 1, 0, p;\n\t}" : "=r"(p));
    return p;
}

#define MBAR_INIT(addr, cnt) \
    asm volatile("mbarrier.init.shared.b64 [%0], %1;" :: "r"(addr), "r"(cnt) : "memory")
#define MBAR_WAIT(addr, parity) do { \
    uint32_t _m = (addr), _p = (parity); \
    asm volatile("{\n\t.reg .pred P;\n\tWL_%=:\n\t" \
        "mbarrier.try_wait.parity.acquire.cta.shared::cta.b64 P, [%0], %1, 0x989680;\n\t" \
        "@P bra.uni WD_%=;\n\tbra.uni WL_%=;\n\tWD_%=:\n\t}" \
        :: "r"(_m), "r"(_p) : "memory"); } while (0)

#define TC_ALLOC(dst, n)  asm volatile("tcgen05.alloc.cta_group::1.sync.aligned.shared::cta.b32 [%0], %1;" :: "r"(dst), "r"(n) : "memory")
#define TC_DEALLOC(t, n)  asm volatile("tcgen05.dealloc.cta_group::1.sync.aligned.b32 %0, %1;" :: "r"(t), "r"(n))
#define TC_RELINQ()       asm volatile("tcgen05.relinquish_alloc_permit.cta_group::1.sync.aligned;")
#define TC_COMMIT(mb)     asm volatile("tcgen05.commit.cta_group::1.mbarrier::arrive::one.shared::cluster.b64 [%0];" :: "r"(mb) : "memory")
#define TC_FENCE_AFTER()  asm volatile("tcgen05.fence::after_thread_sync;" ::: "memory")
#define TC_FENCE_BEFORE() asm volatile("tcgen05.fence::before_thread_sync;" ::: "memory")
#define TC_WAIT_LD()      asm volatile("tcgen05.wait::ld.sync.aligned;" ::: "memory")
#define FENCE_ASYNC()     asm volatile("fence.proxy.async.shared::cta;" ::: "memory")

#define TC_LD_X16(r, addr) \
    asm volatile("tcgen05.ld.sync.aligned.32x32b.x16.b32 " \
        "{%0,%1,%2,%3,%4,%5,%6,%7,%8,%9,%10,%11,%12,%13,%14,%15}, [%16];" \
        : "=r"((r)[0]), "=r"((r)[1]), "=r"((r)[2]), "=r"((r)[3]), \
          "=r"((r)[4]), "=r"((r)[5]), "=r"((r)[6]), "=r"((r)[7]), \
          "=r"((r)[8]), "=r"((r)[9]), "=r"((r)[10]), "=r"((r)[11]), \
          "=r"((r)[12]), "=r"((r)[13]), "=r"((r)[14]), "=r"((r)[15]) \
        : "r"(addr))

#define TC_LD_X32(r, addr) \
    asm volatile("tcgen05.ld.sync.aligned.32x32b.x32.b32 " \
        "{%0,%1,%2,%3,%4,%5,%6,%7,%8,%9,%10,%11,%12,%13,%14,%15," \
        "%16,%17,%18,%19,%20,%21,%22,%23,%24,%25,%26,%27,%28,%29,%30,%31}, [%32];" \
        : "=r"((r)[0]), "=r"((r)[1]), "=r"((r)[2]), "=r"((r)[3]), \
          "=r"((r)[4]), "=r"((r)[5]), "=r"((r)[6]), "=r"((r)[7]), \
          "=r"((r)[8]), "=r"((r)[9]), "=r"((r)[10]), "=r"((r)[11]), \
          "=r"((r)[12]), "=r"((r)[13]), "=r"((r)[14]), "=r"((r)[15]), \
          "=r"((r)[16]), "=r"((r)[17]), "=r"((r)[18]), "=r"((r)[19]), \
          "=r"((r)[20]), "=r"((r)[21]), "=r"((r)[22]), "=r"((r)[23]), \
          "=r"((r)[24]), "=r"((r)[25]), "=r"((r)[26]), "=r"((r)[27]), \
          "=r"((r)[28]), "=r"((r)[29]), "=r"((r)[30]), "=r"((r)[31]) \
        : "r"(addr))

__device__ __forceinline__ void mma_tf32(uint32_t d_tmem, uint64_t a_desc, uint64_t b_desc,
                                         uint32_t idesc, bool acc) {
    uint32_t en = acc ? 1u : 0u;
    asm volatile("{\n\t.reg .pred p;\n\tsetp.ne.u32 p, %5, 0;\n\t"
                 "tcgen05.mma.cta_group::1.kind::tf32 [%0], %1, %2, %3, {%4, %4, %4, %4}, p;\n\t}"
                 :: "r"(d_tmem), "l"(a_desc), "l"(b_desc), "r"(idesc), "r"(0u), "r"(en)
                 : "memory");
}

__device__ __forceinline__ uint64_t mkdesc(uint32_t addr) {
    const uint64_t base = (2ull << 61) | (1ull << 46) | (64ull << 32) | (1ull << 16);
    return base | ((uint64_t)(addr >> 4) & 0x3FFF);
}

#define IDESC_N128 ((1u << 4) | (2u << 7) | (2u << 10) | (16u << 17) | (8u << 24))
#define IDESC_N256 ((1u << 4) | (2u << 7) | (2u << 10) | (32u << 17) | (8u << 24))
#endif  // TC_OK

// ---------------- GEMM1 tcgen05: gate+up, M=256, 4x N=128 dispatches/ks, BK=32, 3-stage ----------------
// TMEM: [0:128)=D0 gate, [128:256)=D0 up, [256:384)=D1 gate, [384:512)=D1 up
__global__ void __launch_bounds__(256, 1) k_gemm1_tc(const float* __restrict__ WgU,
                                                     const float* __restrict__ WuU)
{
#if TC_OK
    int e = blockIdx.z;
    int cnt = g_cnt[e];
    int mpair = blockIdx.x;
    if (mpair * 256 >= cnt) return;
    int base = g_off[e];
    int ntiles = (cnt + 127) >> 7;
    int nt = blockIdx.y;
    int n0 = nt * 128;

    extern __shared__ char dsm[];
    __shared__ uint32_t s_tmem;
    __shared__ uint64_t s_mbar[3];
    uint32_t sbase = (smem_u32(dsm) + 1023) & ~1023u;
    // per stage (64KB): A0 @0, A1 @16K, Bg @32K, Bu @48K
    uint32_t stg[3] = { sbase, sbase + 65536, sbase + 131072 };

    int tid = threadIdx.x, wid = tid >> 5, lane = tid & 31;

    if (tid == 0) {
        MBAR_INIT(smem_u32(&s_mbar[0]), 1);
        MBAR_INIT(smem_u32(&s_mbar[1]), 1);
        MBAR_INIT(smem_u32(&s_mbar[2]), 1);
    }
    if (wid == 0) { TC_ALLOC(smem_u32(&s_tmem), 512); TC_RELINQ(); }
    __syncthreads();
    uint32_t tmem = s_tmem;

    // A gather map: 8 rows per thread across 256 rows
    int c8 = tid & 7;
    const float* asrc[8];
    uint32_t adst[8];
#pragma unroll
    for (int p = 0; p < 8; p++) {
        int r = (tid >> 3) + p * 32;            // 0..255
        int gr = mpair * 256 + r;
        int s = (gr < cnt) ? g_row_src[base + gr] : -1;
        asrc[p] = (s >= 0) ? (g_xr + (size_t)s * HID + c8 * 4) : nullptr;
        int lr = r & 127;
        adst[p] = (uint32_t)((r >> 7) * 16384 + lr * 128 + ((c8 ^ (lr & 7)) * 16));
    }

    const float* tg = g_wg + (((size_t)e * NT1 + nt) * KT1) * 4096 + tid * 16;
    const float* tu = g_wu + (((size_t)e * NT1 + nt) * KT1) * 4096 + tid * 16;
    uint32_t bdst = (uint32_t)(tid * 64);

    auto load_stage = [&](uint32_t bb, int it) {
        int k0 = it * 32;
#pragma unroll
        for (int p = 0; p < 8; p++) {
            if (asrc[p]) cp16(bb + adst[p], asrc[p] + k0);
            else         cp16z(bb + adst[p], g_xr);
        }
        const float* pg = tg + (size_t)it * 4096;
        const float* pu = tu + (size_t)it * 4096;
#pragma unroll
        for (int j = 0; j < 4; j++) {
            cp16(bb + 32768 + bdst + j * 16, pg + j * 4);
            cp16(bb + 49152 + bdst + j * 16, pu + j * 4);
        }
        cp_commit();
    };

    const int KT = KT1;   // 64
    int ph[3] = { 0, 0, 0 };

    load_stage(stg[0], 0);
    load_stage(stg[1], 1);

    for (int it = 0; it < KT; it++) {
        int s = it % 3;
        uint32_t bb = stg[s];
        // Last iteration has only ONE group in flight — drain fully there.
        if (it == KT - 1) cp_wait0(); else cp_wait1();
        __syncthreads();

        if (wid == 0) {
            FENCE_ASYNC();
            if (elect_one()) {
                uint64_t da0 = mkdesc(bb);
                uint64_t da1 = mkdesc(bb + 16384);
                uint64_t dg  = mkdesc(bb + 32768);
                uint64_t du  = mkdesc(bb + 49152);
#pragma unroll
                for (int ks = 0; ks < 4; ks++) {
                    bool acc = !(it == 0 && ks == 0);
                    mma_tf32(tmem,       da0 + 2 * ks, dg + 2 * ks, IDESC_N128, acc);
                    mma_tf32(tmem + 128, da0 + 2 * ks, du + 2 * ks, IDESC_N128, acc);
                    mma_tf32(tmem + 256, da1 + 2 * ks, dg + 2 * ks, IDESC_N128, acc);
                    mma_tf32(tmem + 384, da1 + 2 * ks, du + 2 * ks, IDESC_N128, acc);
                }
                TC_COMMIT(smem_u32(&s_mbar[s]));
            }
        }

        int nx = it + 2;
        if (nx < KT) {
            int sn = nx % 3;     // == (it-1)%3 for it>=1
            if (it >= 1) { MBAR_WAIT(smem_u32(&s_mbar[sn]), ph[sn]); ph[sn] ^= 1; }
            load_stage(stg[sn], nx);
        }
    }

    int ls = (KT - 1) % 3;
    MBAR_WAIT(smem_u32(&s_mbar[ls]), ph[ls]);
    TC_FENCE_AFTER();

    if (wid < 4) {
        int m = wid * 32 + lane;
#pragma unroll
        for (int t = 0; t < 2; t++) {
            int mt = mpair * 2 + t;
            if (mt >= ntiles) break;
            float* dst = g_h + (size_t)(base + mt * 128 + m) * INTER + n0;
#pragma unroll
            for (int c0 = 0; c0 < 128; c0 += 16) {
                uint32_t rg[16], ru[16];
                TC_LD_X16(rg, tmem + t * 256 + c0);
                TC_LD_X16(ru, tmem + t * 256 + 128 + c0);
                TC_WAIT_LD();
#pragma unroll
                for (int j = 0; j < 16; j++) {
                    float g = __uint_as_float(rg[j]);
                    float u = __uint_as_float(ru[j]);
                    float h = (g / (1.f + __expf(-g))) * u;
                    rg[j] = __float_as_uint(tf32r(h));
                }
#pragma unroll
                for (int j = 0; j < 16; j += 4)
                    *(uint4*)(dst + c0 + j) = make_uint4(rg[j], rg[j+1], rg[j+2], rg[j+3]);
            }
        }
        TC_FENCE_BEFORE();
    }
    __syncthreads();
    if (wid == 0) TC_DEALLOC(tmem, 512);
#endif
}

// ---------------- GEMM2 tcgen05: down, M=256, 2x N=256 dispatches/ks, BK=32, 3-stage ----------------
// TMEM: [0:256)=D0, [256:512)=D1
__global__ void __launch_bounds__(256, 1) k_gemm2_tc(const float* __restrict__ WdU)
{
#if TC_OK
    int e = blockIdx.z;
    int cnt = g_cnt[e];
    int mpair = blockIdx.x;
    if (mpair * 256 >= cnt) return;
    int base = g_off[e];
    int ntiles = (cnt + 127) >> 7;
    int nt = blockIdx.y;
    int n0 = nt * 256;

    extern __shared__ char dsm[];
    __shared__ uint32_t s_tmem;
    __shared__ uint64_t s_mbar[3];
    uint32_t sbase = (smem_u32(dsm) + 1023) & ~1023u;
    // per stage (64KB): A0 @0, A1 @16K, B @32K (32KB)
    uint32_t stg[3] = { sbase, sbase + 65536, sbase + 131072 };

    int tid = threadIdx.x, wid = tid >> 5, lane = tid & 31;

    if (tid == 0) {
        MBAR_INIT(smem_u32(&s_mbar[0]), 1);
        MBAR_INIT(smem_u32(&s_mbar[1]), 1);
        MBAR_INIT(smem_u32(&s_mbar[2]), 1);
    }
    if (wid == 0) { TC_ALLOC(smem_u32(&s_tmem), 512); TC_RELINQ(); }
    __syncthreads();
    uint32_t tmem = s_tmem;

    int c8 = tid & 7;
    const float* asrc[8];
    uint32_t adst[8];
#pragma unroll
    for (int p = 0; p < 8; p++) {
        int r = (tid >> 3) + p * 32;
        asrc[p] = g_h + (size_t)(base + mpair * 256 + r) * INTER + c8 * 4;
        int lr = r & 127;
        adst[p] = (uint32_t)((r >> 7) * 16384 + lr * 128 + ((c8 ^ (lr & 7)) * 16));
    }

    const float* td = g_wd + (((size_t)e * NT2 + nt) * KT2) * 8192 + tid * 32;
    uint32_t bdst = (uint32_t)(tid * 128);

    auto load_stage = [&](uint32_t bb, int it) {
        int k0 = it * 32;
#pragma unroll
        for (int p = 0; p < 8; p++)
            cp16(bb + adst[p], asrc[p] + k0);
        const float* pw = td + (size_t)it * 8192;
#pragma unroll
        for (int j = 0; j < 8; j++)
            cp16(bb + 32768 + bdst + j * 16, pw + j * 4);
        cp_commit();
    };

    const int KT = KT2;   // 24
    int ph[3] = { 0, 0, 0 };

    load_stage(stg[0], 0);
    load_stage(stg[1], 1);

    for (int it = 0; it < KT; it++) {
        int s = it % 3;
        uint32_t bb = stg[s];
        if (it == KT - 1) cp_wait0(); else cp_wait1();
        __syncthreads();

        if (wid == 0) {
            FENCE_ASYNC();
            if (elect_one()) {
                uint64_t da0 = mkdesc(bb);
                uint64_t da1 = mkdesc(bb + 16384);
                uint64_t db  = mkdesc(bb + 32768);
#pragma unroll
                for (int ks = 0; ks < 4; ks++) {
                    bool acc = !(it == 0 && ks == 0);
                    mma_tf32(tmem,       da0 + 2 * ks, db + 2 * ks, IDESC_N256, acc);
                    mma_tf32(tmem + 256, da1 + 2 * ks, db + 2 * ks, IDESC_N256, acc);
                }
                TC_COMMIT(smem_u32(&s_mbar[s]));
            }
        }

        int nx = it + 2;
        if (nx < KT) {
            int sn = nx % 3;
            if (it >= 1) { MBAR_WAIT(smem_u32(&s_mbar[sn]), ph[sn]); ph[sn] ^= 1; }
            load_stage(stg[sn], nx);
        }
    }

    int ls = (KT - 1) % 3;
    MBAR_WAIT(smem_u32(&s_mbar[ls]), ph[ls]);
    TC_FENCE_AFTER();

    if (wid < 4) {
        int m = wid * 32 + lane;
#pragma unroll
        for (int t = 0; t < 2; t++) {
            int mt = mpair * 2 + t;
            if (mt >= ntiles) break;
            float* dst = g_down + (size_t)(base + mt * 128 + m) * HID + n0;
#pragma unroll
            for (int c0 = 0; c0 < 256; c0 += 32) {
                uint32_t r[32];
                TC_LD_X32(r, tmem + t * 256 + c0);
                TC_WAIT_LD();
#pragma unroll
                for (int j = 0; j < 32; j += 4)
                    *(uint4*)(dst + c0 + j) = make_uint4(r[j], r[j+1], r[j+2], r[j+3]);
            }
        }
        TC_FENCE_BEFORE();
    }
    __syncthreads();
    if (wid == 0) TC_DEALLOC(tmem, 512);
#endif
}

// ============================================================================
// wmma fallback path (bodies only in non-'a' device passes)
// ============================================================================
#define FBK 16

__global__ void __launch_bounds__(256) k_gemm1_wm(
    const float* __restrict__ x,
    const float* __restrict__ Wg,
    const float* __restrict__ Wu)
{
#if !TC_OK
    int e = blockIdx.z;
    int cnt = g_cnt[e];
    if ((int)blockIdx.x * BM >= cnt) return;
    int base = g_off[e];
    int n0 = blockIdx.y * 64;

    __shared__ float sA [2][BM][FBK + 4];
    __shared__ float sBg[2][FBK][64 + 4];
    __shared__ float sBu[2][FBK][64 + 4];

    int tid = threadIdx.x;
    int wid = tid >> 5;
    int wm = wid >> 1;
    int wn = wid & 1;

    int arow = tid >> 2;
    int acol = (tid & 3) << 2;
    const float* aptr[2];
#pragma unroll
    for (int p = 0; p < 2; p++) {
        int r = blockIdx.x * BM + p * 64 + arow;
        int s = (r < cnt) ? g_row_src[base + r] : -1;
        aptr[p] = (s >= 0) ? (x + (size_t)s * HID + acol) : nullptr;
    }
    int brow = tid >> 4;
    int bcol = (tid & 15) << 2;
    const float* bg = Wg + (size_t)e * HID * INTER + (size_t)brow * INTER + n0 + bcol;
    const float* bu = Wu + (size_t)e * HID * INTER + (size_t)brow * INTER + n0 + bcol;

    wmma::fragment<wmma::accumulator, 16, 16, 8, float> accG[2][2], accU[2][2];
#pragma unroll
    for (int im = 0; im < 2; im++)
#pragma unroll
        for (int in = 0; in < 2; in++) {
            wmma::fill_fragment(accG[im][in], 0.f);
            wmma::fill_fragment(accU[im][in], 0.f);
        }

    auto load_tile = [&](int buf, int k0) {
#pragma unroll
        for (int p = 0; p < 2; p++) {
            uint32_t d = smem_u32(&sA[buf][p * 64 + arow][acol]);
            if (aptr[p]) cp16(d, aptr[p] + k0);
            else         cp16z(d, x);
        }
        cp16(smem_u32(&sBg[buf][brow][bcol]), bg + (size_t)k0 * INTER);
        cp16(smem_u32(&sBu[buf][brow][bcol]), bu + (size_t)k0 * INTER);
    };

    load_tile(0, 0);
    cp_commit();

    int buf = 0;
    for (int k0 = 0; k0 < HID; k0 += FBK) {
        cp_wait0();
        __syncthreads();
        if (k0 + FBK < HID) { load_tile(buf ^ 1, k0 + FBK); cp_commit(); }

#pragma unroll
        for (int kk = 0; kk < FBK; kk += 8) {
            wmma::fragment<wmma::matrix_a, 16, 16, 8, wmma::precision::tf32, wmma::row_major> a[2];
            wmma::fragment<wmma::matrix_b, 16, 16, 8, wmma::precision::tf32, wmma::row_major> fg[2], fu[2];
#pragma unroll
            for (int im = 0; im < 2; im++) {
                wmma::load_matrix_sync(a[im], &sA[buf][wm * 32 + im * 16][kk], FBK + 4);
#pragma unroll
                for (int i = 0; i < a[im].num_elements; i++)
                    a[im].x[i] = wmma::__float_to_tf32(a[im].x[i]);
            }
#pragma unroll
            for (int in = 0; in < 2; in++) {
                wmma::load_matrix_sync(fg[in], &sBg[buf][kk][wn * 32 + in * 16], 64 + 4);
                wmma::load_matrix_sync(fu[in], &sBu[buf][kk][wn * 32 + in * 16], 64 + 4);
#pragma unroll
                for (int i = 0; i < fg[in].num_elements; i++) {
                    fg[in].x[i] = wmma::__float_to_tf32(fg[in].x[i]);
                    fu[in].x[i] = wmma::__float_to_tf32(fu[in].x[i]);
                }
            }
#pragma unroll
            for (int im = 0; im < 2; im++)
#pragma unroll
                for (int in = 0; in < 2; in++) {
                    wmma::mma_sync(accG[im][in], a[im], fg[in], accG[im][in]);
                    wmma::mma_sync(accU[im][in], a[im], fu[in], accU[im][in]);
                }
        }
        buf ^= 1;
    }

#pragma unroll
    for (int im = 0; im < 2; im++)
#pragma unroll
        for (int in = 0; in < 2; in++) {
#pragma unroll
            for (int i = 0; i < accG[im][in].num_elements; i++) {
                float g = accG[im][in].x[i];
                float u = accU[im][in].x[i];
                accG[im][in].x[i] = (g / (1.f + expf(-g))) * u;
            }
            size_t row = (size_t)base + blockIdx.x * BM + wm * 32 + im * 16;
            wmma::store_matrix_sync(g_h + row * INTER + n0 + wn * 32 + in * 16,
                                    accG[im][in], INTER, wmma::mem_row_major);
        }
#endif
}

__global__ void __launch_bounds__(256) k_gemm2_wm(const float* __restrict__ Wd)
{
#if !TC_OK
    int e = blockIdx.z;
    int cnt = g_cnt[e];
    if ((int)blockIdx.x * BM >= cnt) return;
    int base = g_off[e];
    int n0 = blockIdx.y * 64;

    __shared__ float sA[2][BM][FBK + 4];
    __shared__ float sB[2][FBK][64 + 4];

    int tid = threadIdx.x;
    int wid = tid >> 5;
    int wm = wid >> 1;
    int wn = wid & 1;

    int arow = tid >> 2;
    int acol = (tid & 3) << 2;
    const float* A = g_h + (size_t)(base + blockIdx.x * BM) * INTER;

    int brow = tid >> 4;
    int bcol = (tid & 15) << 2;
    const float* B = Wd + (size_t)e * INTER * HID + (size_t)brow * HID + n0 + bcol;

    wmma::fragment<wmma::accumulator, 16, 16, 8, float> acc[2][2];
#pragma unroll
    for (int im = 0; im < 2; im++)
#pragma unroll
        for (int in = 0; in < 2; in++)
            wmma::fill_fragment(acc[im][in], 0.f);

    auto load_tile = [&](int buf, int k0) {
#pragma unroll
        for (int p = 0; p < 2; p++) {
            int r = p * 64 + arow;
            cp16(smem_u32(&sA[buf][r][acol]), A + (size_t)r * INTER + k0 + acol);
        }
        cp16(smem_u32(&sB[buf][brow][bcol]), B + (size_t)k0 * HID);
    };

    load_tile(0, 0);
    cp_commit();

    int buf = 0;
    for (int k0 = 0; k0 < INTER; k0 += FBK) {
        cp_wait0();
        __syncthreads();
        if (k0 + FBK < INTER) { load_tile(buf ^ 1, k0 + FBK); cp_commit(); }

#pragma unroll
        for (int kk = 0; kk < FBK; kk += 8) {
            wmma::fragment<wmma::matrix_a, 16, 16, 8, wmma::precision::tf32, wmma::row_major> a[2];
            wmma::fragment<wmma::matrix_b, 16, 16, 8, wmma::precision::tf32, wmma::row_major> b[2];
#pragma unroll
            for (int im = 0; im < 2; im++) {
                wmma::load_matrix_sync(a[im], &sA[buf][wm * 32 + im * 16][kk], FBK + 4);
#pragma unroll
                for (int i = 0; i < a[im].num_elements; i++)
                    a[im].x[i] = wmma::__float_to_tf32(a[im].x[i]);
            }
#pragma unroll
            for (int in = 0; in < 2; in++) {
                wmma::load_matrix_sync(b[in], &sB[buf][kk][wn * 32 + in * 16], 64 + 4);
#pragma unroll
                for (int i = 0; i < b[in].num_elements; i++)
                    b[in].x[i] = wmma::__float_to_tf32(b[in].x[i]);
            }
#pragma unroll
            for (int im = 0; im < 2; im++)
#pragma unroll
                for (int in = 0; in < 2; in++)
                    wmma::mma_sync(acc[im][in], a[im], b[in], acc[im][in]);
        }
        buf ^= 1;
    }

#pragma unroll
    for (int im = 0; im < 2; im++)
#pragma unroll
        for (int in = 0; in < 2; in++) {
            size_t row = (size_t)base + blockIdx.x * BM + wm * 32 + im * 16;
            wmma::store_matrix_sync(g_down + row * HID + n0 + wn * 32 + in * 16,
                                    acc[im][in], HID, wmma::mem_row_major);
        }
#endif
}

// ---------------- launch ----------------
extern "C" void kernel_launch(void* const* d_in, const int* in_sizes, int n_in,
                              void* d_out, int out_size)
{
    const float* x      = (const float*)d_in[0];
    const float* logits = (const float*)d_in[1];
    const float* Wg     = (const float*)d_in[2];
    const float* Wu     = (const float*)d_in[3];
    const float* Wd     = (const float*)d_in[4];
    float* out = (float*)d_out;

    cudaFuncSetAttribute(k_gemm1_tc, cudaFuncAttributeMaxDynamicSharedMemorySize, 197632);
    cudaFuncSetAttribute(k_gemm2_tc, cudaFuncAttributeMaxDynamicSharedMemorySize, 197632);

    k_zero<<<1, 64>>>();
    k_route<<<(TOKENS + 127) / 128, 128>>>(logits);
    k_scan<<<1, 32>>>();
    k_scatter<<<(TOKENS * TOPK + 255) / 256, 256>>>();
    k_xround<<<(TOKENS * HID / 4 + 255) / 256, 256>>>(x);

    // weight prep: tf32-RN round + K-major SW128 tile bake
    dim3 gp1(KT1, NT1, NEXP);
    k_wprep1<<<gp1, 256>>>(Wg, Wu);
    dim3 gp2(KT2, NT2, NEXP);
    k_wprep2<<<gp2, 256>>>(Wd);

    // tcgen05 path (no-op in non-'a' cubins)
    dim3 g1t(MP_MAX, NT1, NEXP);
    k_gemm1_tc<<<g1t, 256, 197632>>>(Wg, Wu);
    dim3 g2t(MP_MAX, NT2, NEXP);
    k_gemm2_tc<<<g2t, 256, 197632>>>(Wd);

    // wmma fallback path (no-op in 'a' cubins)
    dim3 g1w(TOKENS / BM, INTER / 64, NEXP);
    k_gemm1_wm<<<g1w, 256>>>(x, Wg, Wu);
    dim3 g2w(TOKENS / BM, HID / 64, NEXP);
    k_gemm2_wm<<<g2w, 256>>>(Wd);

    int tot = TOKENS * (HID / 4);
    k_combine<<<(tot + 255) / 256, 256>>>(out);
}